// round 9
// baseline (speedup 1.0000x reference)
#include <cuda_runtime.h>
#include <math_constants.h>

#define B_  8
#define L_  1024
#define S_  1024
#define D_  256
#define V_  256
#define H_  8

#define N_TOK (B_*L_)
#define SCALE_F 0.17677669529663687f

// ---------------- scratch (static device arrays: allocation-free) ----------
// g_qs/g_qo/g_ks/g_ko: tf32 bits, row-major tokens, d-permuted so (d,d+4)
//   are adjacent:  pos = h*32 + 2*p + hi,  p = (dd>>3)*4 + (dd&3), hi=(dd>>2)&1
// g_vh: tf32 bits, blocked [b][sblk=s/8][h][col=32][8] with (s, s+4) adjacent
__device__ float g_qs[N_TOK*D_];
__device__ float g_qo[N_TOK*D_];
__device__ float g_ks[N_TOK*D_];
__device__ float g_ko[N_TOK*D_];
__device__ float g_vh[N_TOK*D_];
__device__ float g_ctx[N_TOK*V_];

// ---------------- fast exp on FMA pipe (rel err ~2e-6) ---------------------
__device__ __forceinline__ float fexp(float x)
{
    float t = fmaxf(x * 1.4426950408889634f, -125.0f);
    float r = rintf(t);
    float f = t - r;
    float p = 1.3333558146428443e-3f;
    p = fmaf(p, f, 9.6181291076284772e-3f);
    p = fmaf(p, f, 5.5504108664821580e-2f);
    p = fmaf(p, f, 2.4022650695910071e-1f);
    p = fmaf(p, f, 6.9314718055994531e-1f);
    p = fmaf(p, f, 1.0f);
    return __int_as_float(__float_as_int(p) + (((int)r) << 23));
}

// ---------------- tf32 mma helpers -----------------------------------------
__device__ __forceinline__ unsigned cvt_tf32(float f)
{
    unsigned r;
    asm("cvt.rna.tf32.f32 %0, %1;" : "=r"(r) : "f"(f));
    return r;
}

__device__ __forceinline__ void mma_tf32(float c[4], const unsigned a[4],
                                         const unsigned b[2])
{
    asm("mma.sync.aligned.m16n8k8.row.col.f32.tf32.tf32.f32 "
        "{%0,%1,%2,%3}, {%4,%5,%6,%7}, {%8,%9}, {%0,%1,%2,%3};"
        : "+f"(c[0]), "+f"(c[1]), "+f"(c[2]), "+f"(c[3])
        : "r"(a[0]), "r"(a[1]), "r"(a[2]), "r"(a[3]),
          "r"(b[0]), "r"(b[1]));
}

// ---------------------------------------------------------------------------
// GEMM (fp32, 8x4 tile, reg prefetch — proven R7 config).
// BM=128, BN=64, BK=16, 256 threads.
// mode 0: plain fp32 row-major (+bias)
// mode 1: tf32, d-pair permuted row-major (q/k scratch)
// mode 2: tf32, s-pair blocked layout (v scratch)
// ---------------------------------------------------------------------------
__device__ __forceinline__ void gemm_body(
    const float* __restrict__ A, const float* __restrict__ Bw,
    float* __restrict__ C, int N, int K,
    float scale, const float* __restrict__ bias, int mode)
{
    const int BM = 128, BN = 64, BK = 16;
    __shared__ __align__(16) float As[BK][BM + 4];
    __shared__ __align__(16) float Bs[BK][BN + 4];

    int t  = threadIdx.x;
    int m0 = blockIdx.y * BM;
    int n0 = blockIdx.x * BN;
    int tx = t & 15;
    int ty = t >> 4;

    float acc[8][4];
#pragma unroll
    for (int i = 0; i < 8; i++)
#pragma unroll
        for (int j = 0; j < 4; j++) acc[i][j] = 0.f;

    const int ra = t >> 2;
    const int ca = (t & 3) * 4;

    float4 pa0 = *reinterpret_cast<const float4*>(&A[(size_t)(m0 + ra) * K + ca]);
    float4 pa1 = *reinterpret_cast<const float4*>(&A[(size_t)(m0 + ra + 64) * K + ca]);
    float4 pb  = *reinterpret_cast<const float4*>(&Bw[(size_t)(n0 + ra) * K + ca]);

    for (int k0 = 0; k0 < K; k0 += BK) {
        As[ca + 0][ra] = pa0.x;  As[ca + 1][ra] = pa0.y;
        As[ca + 2][ra] = pa0.z;  As[ca + 3][ra] = pa0.w;
        As[ca + 0][ra + 64] = pa1.x;  As[ca + 1][ra + 64] = pa1.y;
        As[ca + 2][ra + 64] = pa1.z;  As[ca + 3][ra + 64] = pa1.w;
        Bs[ca + 0][ra] = pb.x;   Bs[ca + 1][ra] = pb.y;
        Bs[ca + 2][ra] = pb.z;   Bs[ca + 3][ra] = pb.w;
        __syncthreads();

        if (k0 + BK < K) {
            int c = k0 + BK + ca;
            pa0 = *reinterpret_cast<const float4*>(&A[(size_t)(m0 + ra) * K + c]);
            pa1 = *reinterpret_cast<const float4*>(&A[(size_t)(m0 + ra + 64) * K + c]);
            pb  = *reinterpret_cast<const float4*>(&Bw[(size_t)(n0 + ra) * K + c]);
        }

#pragma unroll
        for (int k = 0; k < BK; k++) {
            float4 a0 = *reinterpret_cast<const float4*>(&As[k][ty * 8]);
            float4 a1 = *reinterpret_cast<const float4*>(&As[k][ty * 8 + 4]);
            float4 b0 = *reinterpret_cast<const float4*>(&Bs[k][tx * 4]);
            float a[8] = {a0.x, a0.y, a0.z, a0.w, a1.x, a1.y, a1.z, a1.w};
            float bb[4] = {b0.x, b0.y, b0.z, b0.w};
#pragma unroll
            for (int i = 0; i < 8; i++)
#pragma unroll
                for (int j = 0; j < 4; j++) acc[i][j] += a[i] * bb[j];
        }
        __syncthreads();
    }

    if (mode == 0) {
        float bv[4] = {0.f, 0.f, 0.f, 0.f};
        if (bias) {
#pragma unroll
            for (int j = 0; j < 4; j++) bv[j] = bias[n0 + tx * 4 + j];
        }
#pragma unroll
        for (int i = 0; i < 8; i++) {
            int row = m0 + ty * 8 + i;
            float4 o;
            o.x = acc[i][0] * scale + bv[0];
            o.y = acc[i][1] * scale + bv[1];
            o.z = acc[i][2] * scale + bv[2];
            o.w = acc[i][3] * scale + bv[3];
            *reinterpret_cast<float4*>(&C[(size_t)row * N + n0 + tx * 4]) = o;
        }
    } else if (mode == 1) {
#pragma unroll
        for (int i = 0; i < 8; i++) {
            int row = m0 + ty * 8 + i;
#pragma unroll
            for (int j = 0; j < 4; j++) {
                int n  = n0 + tx * 4 + j;
                int hh = n >> 5, dd = n & 31;
                int p  = ((dd >> 3) << 2) | (dd & 3);
                int pos = (hh << 5) + 2 * p + ((dd >> 2) & 1);
                C[(size_t)row * D_ + pos] =
                    __uint_as_float(cvt_tf32(acc[i][j] * scale));
            }
        }
    } else {
#pragma unroll
        for (int i = 0; i < 4; i++) {
            int row  = m0 + ty * 8 + i;
            int bb2  = row >> 10;
            int s    = row & 1023;
            int sblk = s >> 3;
#pragma unroll
            for (int j = 0; j < 4; j++) {
                int n  = n0 + tx * 4 + j;
                int hh = n >> 5, col = n & 31;
                size_t idx = (((size_t)(bb2 * 128 + sblk) * 8 + hh)) * 256 +
                             col * 8 + i * 2;
                float2 o;
                o.x = __uint_as_float(cvt_tf32(acc[i][j]));
                o.y = __uint_as_float(cvt_tf32(acc[i + 4][j]));
                *reinterpret_cast<float2*>(&C[idx]) = o;
            }
        }
    }
}

struct Proj5 {
    const float* A[5];
    const float* W[5];
    float*       C[5];
    float        sc[5];
    int          md[5];
};

__global__ __launch_bounds__(256, 3)
void proj_kernel(Proj5 p)
{
    int z = blockIdx.z;
    gemm_body(p.A[z], p.W[z], p.C[z], D_, D_, p.sc[z], nullptr, p.md[z]);
}

__global__ __launch_bounds__(256, 3)
void fc_kernel(const float* __restrict__ A, const float* __restrict__ W,
               const float* __restrict__ bias, float* __restrict__ C)
{
    gemm_body(A, W, C, V_, V_, 1.0f, bias, 0);
}

// ---------------------------------------------------------------------------
// Attention (tf32 mma, latency-pipelined): block = (b, 32 l-rows), 512 thr.
// Score = self-pass + other-pass, each with distance-2 k-fragment rings.
// PV uses a distance-4 v-fragment ring. attn_out RMW loads hoisted.
// smem floats: score [32][1036] | red [4][32][36] | inv 32 | qid 32 | kid 1024
// ---------------------------------------------------------------------------
#define SC_STR 1036
#define AT_SMEM_BYTES ((32*SC_STR + 4608 + 32 + 32 + 1024) * 4)

__global__ __launch_bounds__(512, 1)
void attn_kernel(const float* __restrict__ mask,
                 const int* __restrict__ qid,
                 const int* __restrict__ kid,
                 float* __restrict__ attn_out)
{
    extern __shared__ float sm[];
    float* score = sm;                        // [32][1036]
    float* red   = sm + 32 * SC_STR;          // [4][32][36]
    float* inv   = red + 4608;                // [32]
    int*   qid_s = (int*)(inv + 32);          // [32]
    int*   kid_s = qid_s + 32;                // [1024]

    const int b    = blockIdx.y;
    const int l0   = blockIdx.x * 32;
    const int t    = threadIdx.x;
    const int lane = t & 31;
    const int w    = t >> 5;                  // 0..15
    const int gid  = lane >> 2;
    const int tid4 = lane & 3;

    const size_t qbase = (size_t)(b * L_ + l0);
    const size_t kbase = (size_t)(b * S_);
    const size_t mrow0 = qbase * S_;

    const int cb = w * 64;                    // score cols for this warp
    const int nc = w & 3;                     // PV col group
    const int sh = w >> 2;                    // PV s-quarter

    for (int i = t; i < S_; i += 512) kid_s[i] = kid[b * S_ + i];
    if (t < 32) qid_s[t] = qid[b * L_ + l0 + t];

    for (int h = 0; h < H_; h++) {
        __syncthreads();   // prev head fully done; ids visible (h=0)

        // ---- A fragments (q self/other): LDG.64 pairs, already tf32 ----
        unsigned aS[2][4][4], aO[2][4][4];
#pragma unroll
        for (int rt = 0; rt < 2; rt++) {
            const size_t r0 = (qbase + rt * 16 + gid) * D_ + h * 32;
            const size_t r1 = (qbase + rt * 16 + gid + 8) * D_ + h * 32;
#pragma unroll
            for (int ks = 0; ks < 4; ks++) {
                int off = 2 * (ks * 4 + tid4);
                uint2 lo = *reinterpret_cast<const uint2*>(&g_qs[r0 + off]);
                uint2 hi = *reinterpret_cast<const uint2*>(&g_qs[r1 + off]);
                aS[rt][ks][0] = lo.x; aS[rt][ks][1] = hi.x;
                aS[rt][ks][2] = lo.y; aS[rt][ks][3] = hi.y;
                lo = *reinterpret_cast<const uint2*>(&g_qo[r0 + off]);
                hi = *reinterpret_cast<const uint2*>(&g_qo[r1 + off]);
                aO[rt][ks][0] = lo.x; aO[rt][ks][1] = hi.x;
                aO[rt][ks][2] = lo.y; aO[rt][ks][3] = hi.y;
            }
        }

        int qi[2][2];
#pragma unroll
        for (int rt = 0; rt < 2; rt++) {
            qi[rt][0] = qid_s[rt * 16 + gid];
            qi[rt][1] = qid_s[rt * 16 + gid + 8];
        }

        // ================= score PASS 1: self (raw values to smem) =========
        {
            unsigned bSb[2][4][2];
#pragma unroll
            for (int pp = 0; pp < 2; pp++) {
                const size_t krow = (kbase + cb + pp * 8 + gid) * D_ + h * 32;
#pragma unroll
                for (int ks = 0; ks < 4; ks++) {
                    int off = 2 * (ks * 4 + tid4);
                    uint2 v = *reinterpret_cast<const uint2*>(&g_ks[krow + off]);
                    bSb[pp][ks][0] = v.x; bSb[pp][ks][1] = v.y;
                }
            }
#pragma unroll
            for (int nt = 0; nt < 8; nt++) {
                const int sl = nt & 1;
                float cS[2][4] = {{0,0,0,0},{0,0,0,0}};
#pragma unroll
                for (int ks = 0; ks < 4; ks++)
#pragma unroll
                    for (int rt = 0; rt < 2; rt++)
                        mma_tf32(cS[rt], aS[rt][ks], bSb[sl][ks]);
                if (nt < 6) {
                    const size_t krow =
                        (kbase + cb + (nt + 2) * 8 + gid) * D_ + h * 32;
#pragma unroll
                    for (int ks = 0; ks < 4; ks++) {
                        int off = 2 * (ks * 4 + tid4);
                        uint2 v = *reinterpret_cast<const uint2*>(
                            &g_ks[krow + off]);
                        bSb[sl][ks][0] = v.x; bSb[sl][ks][1] = v.y;
                    }
                }
                const int scol = cb + nt * 8 + 2 * tid4;
#pragma unroll
                for (int rt = 0; rt < 2; rt++)
#pragma unroll
                    for (int rp = 0; rp < 2; rp++) {
                        int row = rt * 16 + gid + 8 * rp;
                        *reinterpret_cast<float2*>(
                            &score[row * SC_STR + scol]) =
                            make_float2(cS[rt][2*rp], cS[rt][2*rp+1]);
                    }
            }
        }

        // ================= score PASS 2: other + select + mask ==============
        // (same lane reads back its own pass-1 cells — no barrier needed)
        {
            unsigned bOb[2][4][2];
#pragma unroll
            for (int pp = 0; pp < 2; pp++) {
                const size_t krow = (kbase + cb + pp * 8 + gid) * D_ + h * 32;
#pragma unroll
                for (int ks = 0; ks < 4; ks++) {
                    int off = 2 * (ks * 4 + tid4);
                    uint2 v = *reinterpret_cast<const uint2*>(&g_ko[krow + off]);
                    bOb[pp][ks][0] = v.x; bOb[pp][ks][1] = v.y;
                }
            }
#pragma unroll
            for (int nt = 0; nt < 8; nt++) {
                const int sl = nt & 1;
                const int scol = cb + nt * 8 + 2 * tid4;
                int2 ki = *reinterpret_cast<const int2*>(&kid_s[scol]);
                float2 mf[2][2];
#pragma unroll
                for (int rt = 0; rt < 2; rt++)
#pragma unroll
                    for (int rp = 0; rp < 2; rp++) {
                        int row = rt * 16 + gid + 8 * rp;
                        mf[rt][rp] = *reinterpret_cast<const float2*>(
                            &mask[mrow0 + (size_t)row * S_ + scol]);
                    }

                float cO[2][4] = {{0,0,0,0},{0,0,0,0}};
#pragma unroll
                for (int ks = 0; ks < 4; ks++)
#pragma unroll
                    for (int rt = 0; rt < 2; rt++)
                        mma_tf32(cO[rt], aO[rt][ks], bOb[sl][ks]);
                if (nt < 6) {
                    const size_t krow =
                        (kbase + cb + (nt + 2) * 8 + gid) * D_ + h * 32;
#pragma unroll
                    for (int ks = 0; ks < 4; ks++) {
                        int off = 2 * (ks * 4 + tid4);
                        uint2 v = *reinterpret_cast<const uint2*>(
                            &g_ko[krow + off]);
                        bOb[sl][ks][0] = v.x; bOb[sl][ks][1] = v.y;
                    }
                }
#pragma unroll
                for (int rt = 0; rt < 2; rt++)
#pragma unroll
                    for (int rp = 0; rp < 2; rp++) {
                        int row = rt * 16 + gid + 8 * rp;
                        float2 prev = *reinterpret_cast<const float2*>(
                            &score[row * SC_STR + scol]);
                        float v0 = ((qi[rt][rp] == ki.x) ? prev.x
                                                         : cO[rt][2*rp])
                                   + mf[rt][rp].x;
                        float v1 = ((qi[rt][rp] == ki.y) ? prev.y
                                                         : cO[rt][2*rp+1])
                                   + mf[rt][rp].y;
                        *reinterpret_cast<float2*>(
                            &score[row * SC_STR + scol]) =
                            make_float2(v0, v1);
                    }
            }
        }
        __syncthreads();

        // ======= softmax + folded attn-sum (warp w: rows 2w, 2w+1) =========
#pragma unroll
        for (int rr = 0; rr < 2; rr++) {
            int row = 2 * w + rr;
            float4* pr = (float4*)(score + row * SC_STR);
            float4* out4 = reinterpret_cast<float4*>(
                attn_out + mrow0 + (size_t)row * S_);

            float mx = -CUDART_INF_F;
#pragma unroll
            for (int u8 = 0; u8 < 8; u8++) {
                float4 x = pr[lane + 32 * u8];
                mx = fmaxf(mx, fmaxf(fmaxf(x.x, x.y), fmaxf(x.z, x.w)));
            }
#pragma unroll
            for (int o = 16; o > 0; o >>= 1)
                mx = fmaxf(mx, __shfl_xor_sync(0xffffffffu, mx, o));

            // hoist attn_out loads (in flight under the exp pass)
            float4 ov[8];
            if (h > 0) {
#pragma unroll
                for (int u8 = 0; u8 < 8; u8++) ov[u8] = out4[lane + 32 * u8];
            }

            float s = 0.f;
#pragma unroll
            for (int u8 = 0; u8 < 8; u8++) {
                float4 x = pr[lane + 32 * u8];
                x.x = fexp(x.x - mx); x.y = fexp(x.y - mx);
                x.z = fexp(x.z - mx); x.w = fexp(x.w - mx);
                s += (x.x + x.y) + (x.z + x.w);
                pr[lane + 32 * u8] = x;
            }
#pragma unroll
            for (int o = 16; o > 0; o >>= 1)
                s += __shfl_xor_sync(0xffffffffu, s, o);
            float iv = 1.0f / s;
            if (lane == 0) inv[row] = iv;

            float sv = iv * 0.125f;
#pragma unroll
            for (int u8 = 0; u8 < 8; u8++) {
                int u = lane + 32 * u8;
                float4 ev = pr[u];
                float4 o;
                if (h == 0) {
                    o.x = ev.x * sv; o.y = ev.y * sv;
                    o.z = ev.z * sv; o.w = ev.w * sv;
                } else {
                    o.x = fmaf(ev.x, sv, ov[u8].x);
                    o.y = fmaf(ev.y, sv, ov[u8].y);
                    o.z = fmaf(ev.z, sv, ov[u8].z);
                    o.w = fmaf(ev.w, sv, ov[u8].w);
                }
                out4[u] = o;
                float4 rv;
                rv.x = __uint_as_float(cvt_tf32(ev.x));
                rv.y = __uint_as_float(cvt_tf32(ev.y));
                rv.z = __uint_as_float(cvt_tf32(ev.z));
                rv.w = __uint_as_float(cvt_tf32(ev.w));
                pr[u] = rv;
            }
        }
        __syncthreads();

        // ================= PV phase (distance-4 v ring) =================
        float cv[2][4] = {{0,0,0,0},{0,0,0,0}};
        const size_t vbase = ((size_t)(b * 128) * 8 + h) * 256 +
                             (nc * 8 + gid) * 8 + tid4 * 2;
        uint2 vb[4];
#pragma unroll
        for (int i = 0; i < 4; i++)
            vb[i] = *reinterpret_cast<const uint2*>(
                &g_vh[vbase + (size_t)(sh * 32 + i) * 2048]);

#pragma unroll
        for (int kstep = 0; kstep < 32; kstep++) {
            const int sl = kstep & 3;
            unsigned bfrag[2] = {vb[sl].x, vb[sl].y};
            int s8 = sh * 256 + kstep * 8;
#pragma unroll
            for (int rt = 0; rt < 2; rt++) {
                unsigned av[4];
                av[0] = __float_as_uint(score[(rt*16 + gid) * SC_STR + s8 + tid4]);
                av[1] = __float_as_uint(score[(rt*16 + gid + 8) * SC_STR + s8 + tid4]);
                av[2] = __float_as_uint(score[(rt*16 + gid) * SC_STR + s8 + tid4 + 4]);
                av[3] = __float_as_uint(score[(rt*16 + gid + 8) * SC_STR + s8 + tid4 + 4]);
                mma_tf32(cv[rt], av, bfrag);
            }
            if (kstep < 28)
                vb[sl] = *reinterpret_cast<const uint2*>(
                    &g_vh[vbase + (size_t)(sh * 32 + kstep + 4) * 2048]);
        }

        // partials -> red[sh]
#pragma unroll
        for (int rt = 0; rt < 2; rt++)
#pragma unroll
            for (int rp = 0; rp < 2; rp++) {
                int row = rt * 16 + gid + 8 * rp;
                *reinterpret_cast<float2*>(
                    &red[sh * 1152 + row * 36 + nc * 8 + 2 * tid4]) =
                    make_float2(cv[rt][2*rp], cv[rt][2*rp+1]);
            }
        __syncthreads();

        // combine quarters + normalize + write ctx
#pragma unroll
        for (int u = 0; u < 2; u++) {
            int e = t + 512 * u;                   // 0..1023
            int row = e >> 5, d = e & 31;
            float s = red[row * 36 + d] + red[1152 + row * 36 + d] +
                      red[2304 + row * 36 + d] + red[3456 + row * 36 + d];
            g_ctx[(qbase + row) * V_ + h * 32 + d] = s * inv[row];
        }
    }
}

// ---------------------------------------------------------------------------
extern "C" void kernel_launch(void* const* d_in, const int* in_sizes, int n_in,
                              void* d_out, int out_size)
{
    const float* q    = (const float*)d_in[0];
    const float* k    = (const float*)d_in[1];
    const float* v    = (const float*)d_in[2];
    const int*   qid  = (const int*)d_in[3];
    const int*   kid  = (const int*)d_in[4];
    const float* mask = (const float*)d_in[5];
    const float* wqs  = (const float*)d_in[6];
    const float* wqo  = (const float*)d_in[7];
    const float* wks  = (const float*)d_in[8];
    const float* wko  = (const float*)d_in[9];
    const float* wv   = (const float*)d_in[10];
    const float* fcw  = (const float*)d_in[11];
    const float* fcb  = (const float*)d_in[12];

    float* out      = (float*)d_out;
    float* attn_out = out + (size_t)B_ * L_ * V_;

    void *p_qs, *p_qo, *p_ks, *p_ko, *p_vh, *p_ctx;
    cudaGetSymbolAddress(&p_qs,  g_qs);
    cudaGetSymbolAddress(&p_qo,  g_qo);
    cudaGetSymbolAddress(&p_ks,  g_ks);
    cudaGetSymbolAddress(&p_ko,  g_ko);
    cudaGetSymbolAddress(&p_vh,  g_vh);
    cudaGetSymbolAddress(&p_ctx, g_ctx);

    cudaFuncSetAttribute(attn_kernel,
                         cudaFuncAttributeMaxDynamicSharedMemorySize,
                         AT_SMEM_BYTES);

    Proj5 p;
    p.A[0] = q;  p.W[0] = wqs; p.C[0] = (float*)p_qs; p.sc[0] = SCALE_F; p.md[0] = 1;
    p.A[1] = q;  p.W[1] = wqo; p.C[1] = (float*)p_qo; p.sc[1] = SCALE_F; p.md[1] = 1;
    p.A[2] = k;  p.W[2] = wks; p.C[2] = (float*)p_ks; p.sc[2] = 1.0f;    p.md[2] = 1;
    p.A[3] = k;  p.W[3] = wko; p.C[3] = (float*)p_ko; p.sc[3] = 1.0f;    p.md[3] = 1;
    p.A[4] = v;  p.W[4] = wv;  p.C[4] = (float*)p_vh; p.sc[4] = 1.0f;    p.md[4] = 2;

    dim3 pgrid(V_ / 64, N_TOK / 128, 5);    // (4, 64, 5)
    proj_kernel<<<pgrid, 256>>>(p);

    dim3 agrid(L_ / 32, B_);
    attn_kernel<<<agrid, 512, AT_SMEM_BYTES>>>(mask, qid, kid, attn_out);

    dim3 fgrid(V_ / 64, N_TOK / 128);       // (4, 64)
    fc_kernel<<<fgrid, 256>>>((const float*)p_ctx, fcw, fcb, out);
}

// round 10
// speedup vs baseline: 1.3333x; 1.3333x over previous
#include <cuda_runtime.h>
#include <cuda_fp16.h>
#include <math_constants.h>

#define B_  8
#define L_  1024
#define S_  1024
#define D_  256
#define V_  256
#define H_  8

#define N_TOK (B_*L_)
#define SCALE_F 0.17677669529663687f

// ---------------- scratch (static device arrays: allocation-free) ----------
// g_qs/g_qo/g_ks/g_ko: fp16, row-major tokens. Within each head's 32 d:
//   group g = d/16, pair p = (d%16)/2, perm(p) = (p&3)*2 + (p>>2),
//   halfpos = h*32 + g*16 + perm(p)*2 + (d&1)
//   -> m16n8k16 fragment pairs (p=tid4, p=tid4+4) are uint-adjacent (LDG.64).
// g_vh: fp16 blocked [b][sblk16][h][col=32][8 uints], uint pos = perm(p),
//   p = (s%16)/2  -> PV B-fragment (b0,b1) is one LDG.64.
__device__ __half g_qs[N_TOK*D_];
__device__ __half g_qo[N_TOK*D_];
__device__ __half g_ks[N_TOK*D_];
__device__ __half g_ko[N_TOK*D_];
__device__ __half g_vh[N_TOK*D_];
__device__ float  g_ctx[N_TOK*V_];

// ---------------- fast exp on FMA pipe (rel err ~2e-6) ---------------------
__device__ __forceinline__ float fexp(float x)
{
    float t = fmaxf(x * 1.4426950408889634f, -125.0f);
    float r = rintf(t);
    float f = t - r;
    float p = 1.3333558146428443e-3f;
    p = fmaf(p, f, 9.6181291076284772e-3f);
    p = fmaf(p, f, 5.5504108664821580e-2f);
    p = fmaf(p, f, 2.4022650695910071e-1f);
    p = fmaf(p, f, 6.9314718055994531e-1f);
    p = fmaf(p, f, 1.0f);
    return __int_as_float(__float_as_int(p) + (((int)r) << 23));
}

// ---------------- mma helpers -----------------------------------------------
__device__ __forceinline__ void mma_f16(float c[4], const unsigned a[4],
                                        const unsigned b[2])
{
    asm("mma.sync.aligned.m16n8k16.row.col.f32.f16.f16.f32 "
        "{%0,%1,%2,%3}, {%4,%5,%6,%7}, {%8,%9}, {%0,%1,%2,%3};"
        : "+f"(c[0]), "+f"(c[1]), "+f"(c[2]), "+f"(c[3])
        : "r"(a[0]), "r"(a[1]), "r"(a[2]), "r"(a[3]),
          "r"(b[0]), "r"(b[1]));
}

// ---------------------------------------------------------------------------
// GEMM (fp32, 8x4 tile, reg prefetch — proven config). BM=128 BN=64 BK=16.
// mode 0: plain fp32 row-major (+bias)
// mode 1: fp16, pair-permuted row-major (q/k scratch)
// mode 2: fp16, v blocked layout
// ---------------------------------------------------------------------------
__device__ __forceinline__ void gemm_body(
    const float* __restrict__ A, const float* __restrict__ Bw,
    float* __restrict__ C, int N, int K,
    float scale, const float* __restrict__ bias, int mode)
{
    const int BM = 128, BN = 64, BK = 16;
    __shared__ __align__(16) float As[BK][BM + 4];
    __shared__ __align__(16) float Bs[BK][BN + 4];

    int t  = threadIdx.x;
    int m0 = blockIdx.y * BM;
    int n0 = blockIdx.x * BN;
    int tx = t & 15;
    int ty = t >> 4;

    float acc[8][4];
#pragma unroll
    for (int i = 0; i < 8; i++)
#pragma unroll
        for (int j = 0; j < 4; j++) acc[i][j] = 0.f;

    const int ra = t >> 2;
    const int ca = (t & 3) * 4;

    float4 pa0 = *reinterpret_cast<const float4*>(&A[(size_t)(m0 + ra) * K + ca]);
    float4 pa1 = *reinterpret_cast<const float4*>(&A[(size_t)(m0 + ra + 64) * K + ca]);
    float4 pb  = *reinterpret_cast<const float4*>(&Bw[(size_t)(n0 + ra) * K + ca]);

    for (int k0 = 0; k0 < K; k0 += BK) {
        As[ca + 0][ra] = pa0.x;  As[ca + 1][ra] = pa0.y;
        As[ca + 2][ra] = pa0.z;  As[ca + 3][ra] = pa0.w;
        As[ca + 0][ra + 64] = pa1.x;  As[ca + 1][ra + 64] = pa1.y;
        As[ca + 2][ra + 64] = pa1.z;  As[ca + 3][ra + 64] = pa1.w;
        Bs[ca + 0][ra] = pb.x;   Bs[ca + 1][ra] = pb.y;
        Bs[ca + 2][ra] = pb.z;   Bs[ca + 3][ra] = pb.w;
        __syncthreads();

        if (k0 + BK < K) {
            int c = k0 + BK + ca;
            pa0 = *reinterpret_cast<const float4*>(&A[(size_t)(m0 + ra) * K + c]);
            pa1 = *reinterpret_cast<const float4*>(&A[(size_t)(m0 + ra + 64) * K + c]);
            pb  = *reinterpret_cast<const float4*>(&Bw[(size_t)(n0 + ra) * K + c]);
        }

#pragma unroll
        for (int k = 0; k < BK; k++) {
            float4 a0 = *reinterpret_cast<const float4*>(&As[k][ty * 8]);
            float4 a1 = *reinterpret_cast<const float4*>(&As[k][ty * 8 + 4]);
            float4 b0 = *reinterpret_cast<const float4*>(&Bs[k][tx * 4]);
            float a[8] = {a0.x, a0.y, a0.z, a0.w, a1.x, a1.y, a1.z, a1.w};
            float bb[4] = {b0.x, b0.y, b0.z, b0.w};
#pragma unroll
            for (int i = 0; i < 8; i++)
#pragma unroll
                for (int j = 0; j < 4; j++) acc[i][j] += a[i] * bb[j];
        }
        __syncthreads();
    }

    if (mode == 0) {
        float bv[4] = {0.f, 0.f, 0.f, 0.f};
        if (bias) {
#pragma unroll
            for (int j = 0; j < 4; j++) bv[j] = bias[n0 + tx * 4 + j];
        }
#pragma unroll
        for (int i = 0; i < 8; i++) {
            int row = m0 + ty * 8 + i;
            float4 o;
            o.x = acc[i][0] * scale + bv[0];
            o.y = acc[i][1] * scale + bv[1];
            o.z = acc[i][2] * scale + bv[2];
            o.w = acc[i][3] * scale + bv[3];
            *reinterpret_cast<float4*>(&C[(size_t)row * N + n0 + tx * 4]) = o;
        }
    } else if (mode == 1) {
        __half* C16 = reinterpret_cast<__half*>(C);
#pragma unroll
        for (int i = 0; i < 8; i++) {
            int row = m0 + ty * 8 + i;
#pragma unroll
            for (int jp = 0; jp < 4; jp += 2) {
                int n  = n0 + tx * 4 + jp;      // even d
                int hh = n >> 5, d = n & 31;
                int g  = (d >> 4) & 1;
                int p  = (d & 15) >> 1;
                int pm = ((p & 3) << 1) | (p >> 2);
                __half2 hv = __floats2half2_rn(acc[i][jp] * scale,
                                               acc[i][jp + 1] * scale);
                *reinterpret_cast<__half2*>(
                    &C16[(size_t)row * D_ + hh * 32 + g * 16 + pm * 2]) = hv;
            }
        }
    } else {
        __half2* C2 = reinterpret_cast<__half2*>(C);
#pragma unroll
        for (int i = 0; i < 8; i += 2) {
            int row    = m0 + ty * 8 + i;
            int bb2    = row >> 10;
            int s      = row & 1023;
            int sblk16 = s >> 4;
            int pos    = i + (ty & 1);
#pragma unroll
            for (int j = 0; j < 4; j++) {
                int n  = n0 + tx * 4 + j;
                int hh = n >> 5, col = n & 31;
                size_t idx = ((((size_t)(bb2 * 64 + sblk16) * 8 + hh) * 32 +
                               col)) * 8 + pos;
                C2[idx] = __floats2half2_rn(acc[i][j], acc[i + 1][j]);
            }
        }
    }
}

struct Proj5 {
    const float* A[5];
    const float* W[5];
    float*       C[5];
    float        sc[5];
    int          md[5];
};

__global__ __launch_bounds__(256, 3)
void proj_kernel(Proj5 p)
{
    int z = blockIdx.z;
    gemm_body(p.A[z], p.W[z], p.C[z], D_, D_, p.sc[z], nullptr, p.md[z]);
}

__global__ __launch_bounds__(256, 3)
void fc_kernel(const float* __restrict__ A, const float* __restrict__ W,
               const float* __restrict__ bias, float* __restrict__ C)
{
    gemm_body(A, W, C, V_, V_, 1.0f, bias, 0);
}

// ---------------------------------------------------------------------------
// Attention (fp16 m16n8k16 mma): block = (b, 32 l-rows), 512 thr, 1/SM.
// smem floats: score [32][1036] | eh uint[32][516] | red [4][32][36]
//              | inv 32 | qid 32 | kid 1024   = 221,440 B
// ---------------------------------------------------------------------------
#define SC_STR 1036
#define EH_STR 516
#define AT_SMEM_BYTES ((32*SC_STR + 32*EH_STR + 4608 + 32 + 32 + 1024) * 4)

__global__ __launch_bounds__(512, 1)
void attn_kernel(const float* __restrict__ mask,
                 const int* __restrict__ qid,
                 const int* __restrict__ kid,
                 float* __restrict__ attn_out)
{
    extern __shared__ float sm[];
    float*    score = sm;                            // [32][1036] fp32
    unsigned* eh    = (unsigned*)(sm + 32 * SC_STR); // [32][516] half2
    float*    red   = sm + 32 * SC_STR + 32 * EH_STR;// [4][32][36]
    float*    inv   = red + 4608;                    // [32]
    int*      qid_s = (int*)(inv + 32);              // [32]
    int*      kid_s = qid_s + 32;                    // [1024]

    const int b    = blockIdx.y;
    const int l0   = blockIdx.x * 32;
    const int t    = threadIdx.x;
    const int lane = t & 31;
    const int w    = t >> 5;                  // 0..15
    const int gid  = lane >> 2;
    const int tid4 = lane & 3;

    const size_t qbase = (size_t)(b * L_ + l0);
    const size_t kbase = (size_t)(b * S_);
    const size_t mrow0 = qbase * S_;

    const int cb = w * 64;                    // score cols for this warp
    const int nc = w & 3;                     // PV col group
    const int sh = w >> 2;                    // PV s-quarter

    for (int i = t; i < S_; i += 512) kid_s[i] = kid[b * S_ + i];
    if (t < 32) qid_s[t] = qid[b * L_ + l0 + t];

    for (int h = 0; h < H_; h++) {
        __syncthreads();   // prev head fully done; ids visible (h=0)

        // ---- A fragments (q self/other): one LDG.64 per (rt,g,half) ----
        unsigned aS[2][2][4], aO[2][2][4];
#pragma unroll
        for (int rt = 0; rt < 2; rt++) {
            const size_t r0 = (qbase + rt * 16 + gid) * D_ + h * 32;
            const size_t r1 = r0 + 8 * D_;
#pragma unroll
            for (int g = 0; g < 2; g++) {
                int off = g * 16 + 4 * tid4;
                uint2 lo = *reinterpret_cast<const uint2*>(&g_qs[r0 + off]);
                uint2 hi = *reinterpret_cast<const uint2*>(&g_qs[r1 + off]);
                aS[rt][g][0] = lo.x; aS[rt][g][1] = hi.x;
                aS[rt][g][2] = lo.y; aS[rt][g][3] = hi.y;
                lo = *reinterpret_cast<const uint2*>(&g_qo[r0 + off]);
                hi = *reinterpret_cast<const uint2*>(&g_qo[r1 + off]);
                aO[rt][g][0] = lo.x; aO[rt][g][1] = hi.x;
                aO[rt][g][2] = lo.y; aO[rt][g][3] = hi.y;
            }
        }

        int qi[2][2];
#pragma unroll
        for (int rt = 0; rt < 2; rt++) {
            qi[rt][0] = qid_s[rt * 16 + gid];
            qi[rt][1] = qid_s[rt * 16 + gid + 8];
        }

        // ================= score phase (single pass, fp16 mma) =============
#pragma unroll 2
        for (int nt = 0; nt < 8; nt++) {
            const int sK   = cb + nt * 8 + gid;
            const int scol = cb + nt * 8 + 2 * tid4;

            unsigned bS[2][2], bO[2][2];
            const size_t krow = (kbase + sK) * D_ + h * 32;
#pragma unroll
            for (int g = 0; g < 2; g++) {
                int off = g * 16 + 4 * tid4;
                uint2 v = *reinterpret_cast<const uint2*>(&g_ks[krow + off]);
                bS[g][0] = v.x; bS[g][1] = v.y;
                v = *reinterpret_cast<const uint2*>(&g_ko[krow + off]);
                bO[g][0] = v.x; bO[g][1] = v.y;
            }

            int2 ki = *reinterpret_cast<const int2*>(&kid_s[scol]);
            float2 mf[2][2];
#pragma unroll
            for (int rt = 0; rt < 2; rt++)
#pragma unroll
                for (int rp = 0; rp < 2; rp++) {
                    int row = rt * 16 + gid + 8 * rp;
                    mf[rt][rp] = *reinterpret_cast<const float2*>(
                        &mask[mrow0 + (size_t)row * S_ + scol]);
                }

            float cS[2][4] = {{0,0,0,0},{0,0,0,0}};
            float cO[2][4] = {{0,0,0,0},{0,0,0,0}};
#pragma unroll
            for (int g = 0; g < 2; g++)
#pragma unroll
                for (int rt = 0; rt < 2; rt++) {
                    mma_f16(cS[rt], aS[rt][g], bS[g]);
                    mma_f16(cO[rt], aO[rt][g], bO[g]);
                }

#pragma unroll
            for (int rt = 0; rt < 2; rt++)
#pragma unroll
                for (int rp = 0; rp < 2; rp++) {
                    int row = rt * 16 + gid + 8 * rp;
                    float v0 = ((qi[rt][rp] == ki.x) ? cS[rt][2*rp]   : cO[rt][2*rp])   + mf[rt][rp].x;
                    float v1 = ((qi[rt][rp] == ki.y) ? cS[rt][2*rp+1] : cO[rt][2*rp+1]) + mf[rt][rp].y;
                    *reinterpret_cast<float2*>(&score[row * SC_STR + scol]) =
                        make_float2(v0, v1);
                }
        }
        __syncthreads();

        // ======= softmax + folded attn-sum (warp w: rows 2w, 2w+1) =========
#pragma unroll
        for (int rr = 0; rr < 2; rr++) {
            int row = 2 * w + rr;
            float4* pr = (float4*)(score + row * SC_STR);
            unsigned* er = eh + row * EH_STR;
            float4* out4 = reinterpret_cast<float4*>(
                attn_out + mrow0 + (size_t)row * S_);

            float mx = -CUDART_INF_F;
#pragma unroll
            for (int u8 = 0; u8 < 8; u8++) {
                float4 x = pr[lane + 32 * u8];
                mx = fmaxf(mx, fmaxf(fmaxf(x.x, x.y), fmaxf(x.z, x.w)));
            }
#pragma unroll
            for (int o = 16; o > 0; o >>= 1)
                mx = fmaxf(mx, __shfl_xor_sync(0xffffffffu, mx, o));

            float4 ov[8];
            if (h > 0) {
#pragma unroll
                for (int u8 = 0; u8 < 8; u8++) ov[u8] = out4[lane + 32 * u8];
            }

            float s = 0.f;
#pragma unroll
            for (int u8 = 0; u8 < 8; u8++) {
                float4 x = pr[lane + 32 * u8];
                x.x = fexp(x.x - mx); x.y = fexp(x.y - mx);
                x.z = fexp(x.z - mx); x.w = fexp(x.w - mx);
                s += (x.x + x.y) + (x.z + x.w);
                pr[lane + 32 * u8] = x;
                __half2 h01 = __floats2half2_rn(x.x, x.y);
                __half2 h23 = __floats2half2_rn(x.z, x.w);
                uint2 ev;
                ev.x = *reinterpret_cast<unsigned*>(&h01);
                ev.y = *reinterpret_cast<unsigned*>(&h23);
                *reinterpret_cast<uint2*>(&er[2 * (lane + 32 * u8)]) = ev;
            }
#pragma unroll
            for (int o = 16; o > 0; o >>= 1)
                s += __shfl_xor_sync(0xffffffffu, s, o);
            float iv = 1.0f / s;
            if (lane == 0) inv[row] = iv;

            float sv = iv * 0.125f;
#pragma unroll
            for (int u8 = 0; u8 < 8; u8++) {
                int u = lane + 32 * u8;
                float4 e = pr[u];
                float4 o;
                if (h == 0) {
                    o.x = e.x * sv; o.y = e.y * sv;
                    o.z = e.z * sv; o.w = e.w * sv;
                } else {
                    o.x = fmaf(e.x, sv, ov[u8].x);
                    o.y = fmaf(e.y, sv, ov[u8].y);
                    o.z = fmaf(e.z, sv, ov[u8].z);
                    o.w = fmaf(e.w, sv, ov[u8].w);
                }
                out4[u] = o;
            }
        }
        __syncthreads();

        // ================= PV phase (fp16 m16n8k16) =================
        float cv[2][4] = {{0,0,0,0},{0,0,0,0}};
        const size_t vb0 = ((((size_t)(b * 64 + sh * 16) * 8 + h) * 32 +
                             nc * 8 + gid)) * 8 + 2 * tid4;
        const unsigned* vh_u = reinterpret_cast<const unsigned*>(g_vh);

#pragma unroll 4
        for (int kstep = 0; kstep < 16; kstep++) {
            uint2 bvv = *reinterpret_cast<const uint2*>(
                &vh_u[vb0 + (size_t)kstep * 2048]);
            unsigned bfrag[2] = {bvv.x, bvv.y};
            const int k8 = sh * 128 + kstep * 8;    // half2-pair base
#pragma unroll
            for (int rt = 0; rt < 2; rt++) {
                unsigned av[4];
                av[0] = eh[(rt*16 + gid) * EH_STR + k8 + tid4];
                av[1] = eh[(rt*16 + gid + 8) * EH_STR + k8 + tid4];
                av[2] = eh[(rt*16 + gid) * EH_STR + k8 + tid4 + 4];
                av[3] = eh[(rt*16 + gid + 8) * EH_STR + k8 + tid4 + 4];
                mma_f16(cv[rt], av, bfrag);
            }
        }

        // partials -> red[sh]
#pragma unroll
        for (int rt = 0; rt < 2; rt++)
#pragma unroll
            for (int rp = 0; rp < 2; rp++) {
                int row = rt * 16 + gid + 8 * rp;
                *reinterpret_cast<float2*>(
                    &red[sh * 1152 + row * 36 + nc * 8 + 2 * tid4]) =
                    make_float2(cv[rt][2*rp], cv[rt][2*rp+1]);
            }
        __syncthreads();

        // combine quarters + normalize + write ctx
#pragma unroll
        for (int u = 0; u < 2; u++) {
            int e = t + 512 * u;                   // 0..1023
            int row = e >> 5, d = e & 31;
            float s = red[row * 36 + d] + red[1152 + row * 36 + d] +
                      red[2304 + row * 36 + d] + red[3456 + row * 36 + d];
            g_ctx[(qbase + row) * V_ + h * 32 + d] = s * inv[row];
        }
    }
}

// ---------------------------------------------------------------------------
extern "C" void kernel_launch(void* const* d_in, const int* in_sizes, int n_in,
                              void* d_out, int out_size)
{
    const float* q    = (const float*)d_in[0];
    const float* k    = (const float*)d_in[1];
    const float* v    = (const float*)d_in[2];
    const int*   qid  = (const int*)d_in[3];
    const int*   kid  = (const int*)d_in[4];
    const float* mask = (const float*)d_in[5];
    const float* wqs  = (const float*)d_in[6];
    const float* wqo  = (const float*)d_in[7];
    const float* wks  = (const float*)d_in[8];
    const float* wko  = (const float*)d_in[9];
    const float* wv   = (const float*)d_in[10];
    const float* fcw  = (const float*)d_in[11];
    const float* fcb  = (const float*)d_in[12];

    float* out      = (float*)d_out;
    float* attn_out = out + (size_t)B_ * L_ * V_;

    void *p_qs, *p_qo, *p_ks, *p_ko, *p_vh, *p_ctx;
    cudaGetSymbolAddress(&p_qs,  g_qs);
    cudaGetSymbolAddress(&p_qo,  g_qo);
    cudaGetSymbolAddress(&p_ks,  g_ks);
    cudaGetSymbolAddress(&p_ko,  g_ko);
    cudaGetSymbolAddress(&p_vh,  g_vh);
    cudaGetSymbolAddress(&p_ctx, g_ctx);

    cudaFuncSetAttribute(attn_kernel,
                         cudaFuncAttributeMaxDynamicSharedMemorySize,
                         AT_SMEM_BYTES);

    Proj5 p;
    p.A[0] = q;  p.W[0] = wqs; p.C[0] = (float*)p_qs; p.sc[0] = SCALE_F; p.md[0] = 1;
    p.A[1] = q;  p.W[1] = wqo; p.C[1] = (float*)p_qo; p.sc[1] = SCALE_F; p.md[1] = 1;
    p.A[2] = k;  p.W[2] = wks; p.C[2] = (float*)p_ks; p.sc[2] = 1.0f;    p.md[2] = 1;
    p.A[3] = k;  p.W[3] = wko; p.C[3] = (float*)p_ko; p.sc[3] = 1.0f;    p.md[3] = 1;
    p.A[4] = v;  p.W[4] = wv;  p.C[4] = (float*)p_vh; p.sc[4] = 1.0f;    p.md[4] = 2;

    dim3 pgrid(V_ / 64, N_TOK / 128, 5);    // (4, 64, 5)
    proj_kernel<<<pgrid, 256>>>(p);

    dim3 agrid(L_ / 32, B_);
    attn_kernel<<<agrid, 512, AT_SMEM_BYTES>>>(mask, qid, kid, attn_out);

    dim3 fgrid(V_ / 64, N_TOK / 128);       // (4, 64)
    fc_kernel<<<fgrid, 256>>>((const float*)p_ctx, fcw, fcb, out);
}

// round 11
// speedup vs baseline: 1.5192x; 1.1394x over previous
#include <cuda_runtime.h>
#include <cuda_fp16.h>
#include <math_constants.h>

#define B_  8
#define L_  1024
#define S_  1024
#define D_  256
#define V_  256
#define H_  8

#define N_TOK (B_*L_)
#define SCALE_F 0.17677669529663687f

// pair permutation for m16n8k16 fragment adjacency: p in 0..7
__host__ __device__ __forceinline__ int permp(int p)
{
    return ((p & 3) << 1) | (p >> 2);
}

// ---------------- scratch (static device arrays: allocation-free) ----------
// fp16 pair-permuted row-major (K=256):
//   pos(n) = (n & ~15) + permp((n&15)>>1)*2 + (n&1)
__device__ __half g_qf[N_TOK*D_];    // q input, fp16 permuted
__device__ __half g_kf[N_TOK*D_];
__device__ __half g_vf[N_TOK*D_];
__device__ __half g_wqs[D_*D_], g_wqo[D_*D_], g_wks[D_*D_];
__device__ __half g_wko[D_*D_], g_wv[D_*D_], g_fcwh[V_*V_];

__device__ __half g_qs[N_TOK*D_];    // projected q self (permuted fp16)
__device__ __half g_qo[N_TOK*D_];
__device__ __half g_ks[N_TOK*D_];
__device__ __half g_ko[N_TOK*D_];
__device__ __half g_vh[N_TOK*D_];    // v blocked layout (R10)
__device__ __half g_ctx[N_TOK*V_];   // ctx, permuted fp16 (fc A operand)

// ---------------- fast exp on FMA pipe (rel err ~2e-6) ---------------------
__device__ __forceinline__ float fexp(float x)
{
    float t = fmaxf(x * 1.4426950408889634f, -125.0f);
    float r = rintf(t);
    float f = t - r;
    float p = 1.3333558146428443e-3f;
    p = fmaf(p, f, 9.6181291076284772e-3f);
    p = fmaf(p, f, 5.5504108664821580e-2f);
    p = fmaf(p, f, 2.4022650695910071e-1f);
    p = fmaf(p, f, 6.9314718055994531e-1f);
    p = fmaf(p, f, 1.0f);
    return __int_as_float(__float_as_int(p) + (((int)r) << 23));
}

__device__ __forceinline__ void mma_f16(float c[4], const unsigned a[4],
                                        const unsigned b[2])
{
    asm("mma.sync.aligned.m16n8k16.row.col.f32.f16.f16.f32 "
        "{%0,%1,%2,%3}, {%4,%5,%6,%7}, {%8,%9}, {%0,%1,%2,%3};"
        : "+f"(c[0]), "+f"(c[1]), "+f"(c[2]), "+f"(c[3])
        : "r"(a[0]), "r"(a[1]), "r"(a[2]), "r"(a[3]),
          "r"(b[0]), "r"(b[1]));
}

// ---------------------------------------------------------------------------
// Prep: fp32 -> fp16 pair-permuted (K=256 rows). One half2 per thread-iter.
// ---------------------------------------------------------------------------
struct Prep9 {
    const float* src[9];
    __half*      dst[9];
    int          n[9];      // element count (multiple of 512)
};

__global__ __launch_bounds__(256)
void prep_kernel(Prep9 P)
{
    int z = blockIdx.y;
    int idx = blockIdx.x * 256 + threadIdx.x;
    int i2 = idx * 2;
    if (i2 >= P.n[z]) return;
    float2 v = *reinterpret_cast<const float2*>(&P.src[z][i2]);
    int c = i2 & 255;
    int pos = (c & ~15) + permp((c & 15) >> 1) * 2;
    *reinterpret_cast<__half2*>(&P.dst[z][(size_t)(i2 >> 8) * 256 + pos]) =
        __floats2half2_rn(v.x, v.y);
}

// ---------------------------------------------------------------------------
// gemm16: C[M,256] = scale*(A @ W^T)  with fp16 m16n8k16 mma, fragment-fed.
// A, W: fp16 pair-permuted row-major (as unsigned*). 256 threads, 8 warps.
// Block tile: m 128 x n 128. Warp: m 32 x n 64.
// mode 0: fp32 row-major + bias | mode 1: fp16 permuted | mode 2: v blocked
// ---------------------------------------------------------------------------
__device__ __forceinline__ void gemm16_body(
    const unsigned* __restrict__ A, const unsigned* __restrict__ Bw,
    void* __restrict__ Cout, float scale, int mode,
    const float* __restrict__ bias)
{
    const int t    = threadIdx.x;
    const int w    = t >> 5;
    const int lane = t & 31;
    const int gid  = lane >> 2;
    const int tid4 = lane & 3;

    const int m0 = blockIdx.y * 128 + (w & 3) * 32;
    const int n0 = blockIdx.x * 128 + (w >> 2) * 64;

    float c[2][8][4];
#pragma unroll
    for (int rt = 0; rt < 2; rt++)
#pragma unroll
        for (int nt = 0; nt < 8; nt++)
#pragma unroll
            for (int e = 0; e < 4; e++) c[rt][nt][e] = 0.f;

#pragma unroll 4
    for (int kg = 0; kg < 16; kg++) {
        const int ko = kg * 8 + 2 * tid4;
        unsigned a[2][4];
#pragma unroll
        for (int rt = 0; rt < 2; rt++) {
            uint2 lo = *reinterpret_cast<const uint2*>(
                &A[(size_t)(m0 + rt * 16 + gid) * 128 + ko]);
            uint2 hi = *reinterpret_cast<const uint2*>(
                &A[(size_t)(m0 + rt * 16 + gid + 8) * 128 + ko]);
            a[rt][0] = lo.x; a[rt][1] = hi.x;
            a[rt][2] = lo.y; a[rt][3] = hi.y;
        }
#pragma unroll
        for (int nt = 0; nt < 8; nt++) {
            uint2 bb = *reinterpret_cast<const uint2*>(
                &Bw[(size_t)(n0 + nt * 8 + gid) * 128 + ko]);
            unsigned bfr[2] = {bb.x, bb.y};
            mma_f16(c[0][nt], a[0], bfr);
            mma_f16(c[1][nt], a[1], bfr);
        }
    }

    if (mode == 0) {
        float* Cf = (float*)Cout;
#pragma unroll
        for (int nt = 0; nt < 8; nt++) {
            int col = n0 + nt * 8 + 2 * tid4;
            float b0 = bias ? bias[col] : 0.f;
            float b1 = bias ? bias[col + 1] : 0.f;
#pragma unroll
            for (int rt = 0; rt < 2; rt++) {
                int r0 = m0 + rt * 16 + gid;
                *reinterpret_cast<float2*>(&Cf[(size_t)r0 * 256 + col]) =
                    make_float2(c[rt][nt][0] * scale + b0,
                                c[rt][nt][1] * scale + b1);
                *reinterpret_cast<float2*>(&Cf[(size_t)(r0 + 8) * 256 + col]) =
                    make_float2(c[rt][nt][2] * scale + b0,
                                c[rt][nt][3] * scale + b1);
            }
        }
    } else if (mode == 1) {
        __half* Ch = (__half*)Cout;
#pragma unroll
        for (int nt = 0; nt < 8; nt++) {
            int col = n0 + nt * 8 + 2 * tid4;   // even
            int pos = (col & ~15) + permp((col & 15) >> 1) * 2;
#pragma unroll
            for (int rt = 0; rt < 2; rt++) {
                int r0 = m0 + rt * 16 + gid;
                *reinterpret_cast<__half2*>(&Ch[(size_t)r0 * 256 + pos]) =
                    __floats2half2_rn(c[rt][nt][0] * scale,
                                      c[rt][nt][1] * scale);
                *reinterpret_cast<__half2*>(&Ch[(size_t)(r0 + 8) * 256 + pos]) =
                    __floats2half2_rn(c[rt][nt][2] * scale,
                                      c[rt][nt][3] * scale);
            }
        }
    } else {
        // v blocked: halfidx = (((b*64+sblk16)*8+hh)*32+col32)*16
        //            + permp((s&15)>>1)*2 + (s&1)
        __half* Ch = (__half*)Cout;
#pragma unroll
        for (int rt = 0; rt < 2; rt++)
#pragma unroll
            for (int rp = 0; rp < 2; rp++) {
                int r  = m0 + rt * 16 + gid + 8 * rp;
                int bb2 = r >> 10;
                int s  = r & 1023;
                int ph = permp((s & 15) >> 1) * 2 + (s & 1);
                size_t base0 = ((size_t)(bb2 * 64 + (s >> 4))) * 8;
#pragma unroll
                for (int nt = 0; nt < 8; nt++) {
#pragma unroll
                    for (int e = 0; e < 2; e++) {
                        int n = n0 + nt * 8 + 2 * tid4 + e;
                        size_t hi = ((base0 + (n >> 5)) * 32 + (n & 31)) * 16 + ph;
                        Ch[hi] = __float2half(c[rt][nt][2 * rp + e]);
                    }
                }
            }
    }
}

struct G5 {
    const unsigned* A[5];
    const unsigned* W[5];
    void*           C[5];
    float           sc[5];
    int             md[5];
};

__global__ __launch_bounds__(256, 2)
void proj16_kernel(G5 g)
{
    int z = blockIdx.z;
    gemm16_body(g.A[z], g.W[z], g.C[z], g.sc[z], g.md[z], nullptr);
}

__global__ __launch_bounds__(256, 2)
void fc16_kernel(const unsigned* __restrict__ A, const unsigned* __restrict__ W,
                 float* __restrict__ C, const float* __restrict__ bias)
{
    gemm16_body(A, W, C, 1.0f, 0, bias);
}

// ---------------------------------------------------------------------------
// Attention (fp16 m16n8k16 mma) — R10 structure, ctx written as permuted fp16.
// smem floats: score [32][1036] | eh uint[32][516] | red [4][32][36]
//              | inv 32 | qid 32 | kid 1024
// ---------------------------------------------------------------------------
#define SC_STR 1036
#define EH_STR 516
#define AT_SMEM_BYTES ((32*SC_STR + 32*EH_STR + 4608 + 32 + 32 + 1024) * 4)

__global__ __launch_bounds__(512, 1)
void attn_kernel(const float* __restrict__ mask,
                 const int* __restrict__ qid,
                 const int* __restrict__ kid,
                 float* __restrict__ attn_out)
{
    extern __shared__ float sm[];
    float*    score = sm;                            // [32][1036] fp32
    unsigned* eh    = (unsigned*)(sm + 32 * SC_STR); // [32][516] half2
    float*    red   = sm + 32 * SC_STR + 32 * EH_STR;// [4][32][36]
    float*    inv   = red + 4608;                    // [32]
    int*      qid_s = (int*)(inv + 32);              // [32]
    int*      kid_s = qid_s + 32;                    // [1024]

    const int b    = blockIdx.y;
    const int l0   = blockIdx.x * 32;
    const int t    = threadIdx.x;
    const int lane = t & 31;
    const int w    = t >> 5;                  // 0..15
    const int gid  = lane >> 2;
    const int tid4 = lane & 3;

    const size_t qbase = (size_t)(b * L_ + l0);
    const size_t kbase = (size_t)(b * S_);
    const size_t mrow0 = qbase * S_;

    const int cb = w * 64;                    // score cols for this warp
    const int nc = w & 3;                     // PV col group
    const int sh = w >> 2;                    // PV s-quarter

    for (int i = t; i < S_; i += 512) kid_s[i] = kid[b * S_ + i];
    if (t < 32) qid_s[t] = qid[b * L_ + l0 + t];

    for (int h = 0; h < H_; h++) {
        __syncthreads();   // prev head fully done; ids visible (h=0)

        // ---- A fragments (q self/other): one LDG.64 per (rt,g,half) ----
        unsigned aS[2][2][4], aO[2][2][4];
#pragma unroll
        for (int rt = 0; rt < 2; rt++) {
            const size_t r0 = (qbase + rt * 16 + gid) * D_ + h * 32;
            const size_t r1 = r0 + 8 * D_;
#pragma unroll
            for (int g = 0; g < 2; g++) {
                int off = g * 16 + 4 * tid4;
                uint2 lo = *reinterpret_cast<const uint2*>(&g_qs[r0 + off]);
                uint2 hi = *reinterpret_cast<const uint2*>(&g_qs[r1 + off]);
                aS[rt][g][0] = lo.x; aS[rt][g][1] = hi.x;
                aS[rt][g][2] = lo.y; aS[rt][g][3] = hi.y;
                lo = *reinterpret_cast<const uint2*>(&g_qo[r0 + off]);
                hi = *reinterpret_cast<const uint2*>(&g_qo[r1 + off]);
                aO[rt][g][0] = lo.x; aO[rt][g][1] = hi.x;
                aO[rt][g][2] = lo.y; aO[rt][g][3] = hi.y;
            }
        }

        int qi[2][2];
#pragma unroll
        for (int rt = 0; rt < 2; rt++) {
            qi[rt][0] = qid_s[rt * 16 + gid];
            qi[rt][1] = qid_s[rt * 16 + gid + 8];
        }

        // ================= score phase (single pass, fp16 mma) =============
#pragma unroll 2
        for (int nt = 0; nt < 8; nt++) {
            const int sK   = cb + nt * 8 + gid;
            const int scol = cb + nt * 8 + 2 * tid4;

            unsigned bS[2][2], bO[2][2];
            const size_t krow = (kbase + sK) * D_ + h * 32;
#pragma unroll
            for (int g = 0; g < 2; g++) {
                int off = g * 16 + 4 * tid4;
                uint2 v = *reinterpret_cast<const uint2*>(&g_ks[krow + off]);
                bS[g][0] = v.x; bS[g][1] = v.y;
                v = *reinterpret_cast<const uint2*>(&g_ko[krow + off]);
                bO[g][0] = v.x; bO[g][1] = v.y;
            }

            int2 ki = *reinterpret_cast<const int2*>(&kid_s[scol]);
            float2 mf[2][2];
#pragma unroll
            for (int rt = 0; rt < 2; rt++)
#pragma unroll
                for (int rp = 0; rp < 2; rp++) {
                    int row = rt * 16 + gid + 8 * rp;
                    mf[rt][rp] = *reinterpret_cast<const float2*>(
                        &mask[mrow0 + (size_t)row * S_ + scol]);
                }

            float cS[2][4] = {{0,0,0,0},{0,0,0,0}};
            float cO[2][4] = {{0,0,0,0},{0,0,0,0}};
#pragma unroll
            for (int g = 0; g < 2; g++)
#pragma unroll
                for (int rt = 0; rt < 2; rt++) {
                    mma_f16(cS[rt], aS[rt][g], bS[g]);
                    mma_f16(cO[rt], aO[rt][g], bO[g]);
                }

#pragma unroll
            for (int rt = 0; rt < 2; rt++)
#pragma unroll
                for (int rp = 0; rp < 2; rp++) {
                    int row = rt * 16 + gid + 8 * rp;
                    float v0 = ((qi[rt][rp] == ki.x) ? cS[rt][2*rp]   : cO[rt][2*rp])   + mf[rt][rp].x;
                    float v1 = ((qi[rt][rp] == ki.y) ? cS[rt][2*rp+1] : cO[rt][2*rp+1]) + mf[rt][rp].y;
                    *reinterpret_cast<float2*>(&score[row * SC_STR + scol]) =
                        make_float2(v0, v1);
                }
        }
        __syncthreads();

        // ======= softmax + folded attn-sum (warp w: rows 2w, 2w+1) =========
#pragma unroll
        for (int rr = 0; rr < 2; rr++) {
            int row = 2 * w + rr;
            float4* pr = (float4*)(score + row * SC_STR);
            unsigned* er = eh + row * EH_STR;
            float4* out4 = reinterpret_cast<float4*>(
                attn_out + mrow0 + (size_t)row * S_);

            float mx = -CUDART_INF_F;
#pragma unroll
            for (int u8 = 0; u8 < 8; u8++) {
                float4 x = pr[lane + 32 * u8];
                mx = fmaxf(mx, fmaxf(fmaxf(x.x, x.y), fmaxf(x.z, x.w)));
            }
#pragma unroll
            for (int o = 16; o > 0; o >>= 1)
                mx = fmaxf(mx, __shfl_xor_sync(0xffffffffu, mx, o));

            float4 ov[8];
            if (h > 0) {
#pragma unroll
                for (int u8 = 0; u8 < 8; u8++) ov[u8] = out4[lane + 32 * u8];
            }

            float s = 0.f;
#pragma unroll
            for (int u8 = 0; u8 < 8; u8++) {
                float4 x = pr[lane + 32 * u8];
                x.x = fexp(x.x - mx); x.y = fexp(x.y - mx);
                x.z = fexp(x.z - mx); x.w = fexp(x.w - mx);
                s += (x.x + x.y) + (x.z + x.w);
                pr[lane + 32 * u8] = x;
                __half2 h01 = __floats2half2_rn(x.x, x.y);
                __half2 h23 = __floats2half2_rn(x.z, x.w);
                uint2 ev;
                ev.x = *reinterpret_cast<unsigned*>(&h01);
                ev.y = *reinterpret_cast<unsigned*>(&h23);
                *reinterpret_cast<uint2*>(&er[2 * (lane + 32 * u8)]) = ev;
            }
#pragma unroll
            for (int o = 16; o > 0; o >>= 1)
                s += __shfl_xor_sync(0xffffffffu, s, o);
            float iv = 1.0f / s;
            if (lane == 0) inv[row] = iv;

            float sv = iv * 0.125f;
#pragma unroll
            for (int u8 = 0; u8 < 8; u8++) {
                int u = lane + 32 * u8;
                float4 e = pr[u];
                float4 o;
                if (h == 0) {
                    o.x = e.x * sv; o.y = e.y * sv;
                    o.z = e.z * sv; o.w = e.w * sv;
                } else {
                    o.x = fmaf(e.x, sv, ov[u8].x);
                    o.y = fmaf(e.y, sv, ov[u8].y);
                    o.z = fmaf(e.z, sv, ov[u8].z);
                    o.w = fmaf(e.w, sv, ov[u8].w);
                }
                out4[u] = o;
            }
        }
        __syncthreads();

        // ================= PV phase (fp16 m16n8k16) =================
        float cv[2][4] = {{0,0,0,0},{0,0,0,0}};
        const size_t vb0 = ((((size_t)(b * 64 + sh * 16) * 8 + h) * 32 +
                             nc * 8 + gid)) * 8 + 2 * tid4;
        const unsigned* vh_u = reinterpret_cast<const unsigned*>(g_vh);

#pragma unroll 4
        for (int kstep = 0; kstep < 16; kstep++) {
            uint2 bvv = *reinterpret_cast<const uint2*>(
                &vh_u[vb0 + (size_t)kstep * 2048]);
            unsigned bfrag[2] = {bvv.x, bvv.y};
            const int k8 = sh * 128 + kstep * 8;
#pragma unroll
            for (int rt = 0; rt < 2; rt++) {
                unsigned av[4];
                av[0] = eh[(rt*16 + gid) * EH_STR + k8 + tid4];
                av[1] = eh[(rt*16 + gid + 8) * EH_STR + k8 + tid4];
                av[2] = eh[(rt*16 + gid) * EH_STR + k8 + tid4 + 4];
                av[3] = eh[(rt*16 + gid + 8) * EH_STR + k8 + tid4 + 4];
                mma_f16(cv[rt], av, bfrag);
            }
        }

        // partials -> red[sh]
#pragma unroll
        for (int rt = 0; rt < 2; rt++)
#pragma unroll
            for (int rp = 0; rp < 2; rp++) {
                int row = rt * 16 + gid + 8 * rp;
                *reinterpret_cast<float2*>(
                    &red[sh * 1152 + row * 36 + nc * 8 + 2 * tid4]) =
                    make_float2(cv[rt][2*rp], cv[rt][2*rp+1]);
            }
        __syncthreads();

        // combine quarters + normalize + write ctx as permuted fp16 (fc A)
        {
            int row = t >> 4;
            int d0  = (t & 15) * 2;
            float s0 = red[row * 36 + d0]        + red[1152 + row * 36 + d0] +
                       red[2304 + row * 36 + d0] + red[3456 + row * 36 + d0];
            float s1 = red[row * 36 + d0 + 1]        + red[1152 + row * 36 + d0 + 1] +
                       red[2304 + row * 36 + d0 + 1] + red[3456 + row * 36 + d0 + 1];
            float iv = inv[row];
            int n = h * 32 + d0;
            int pos = (n & ~15) + permp((n & 15) >> 1) * 2;
            *reinterpret_cast<__half2*>(&g_ctx[(qbase + row) * 256 + pos]) =
                __floats2half2_rn(s0 * iv, s1 * iv);
        }
    }
}

// ---------------------------------------------------------------------------
extern "C" void kernel_launch(void* const* d_in, const int* in_sizes, int n_in,
                              void* d_out, int out_size)
{
    const float* q    = (const float*)d_in[0];
    const float* k    = (const float*)d_in[1];
    const float* v    = (const float*)d_in[2];
    const int*   qid  = (const int*)d_in[3];
    const int*   kid  = (const int*)d_in[4];
    const float* mask = (const float*)d_in[5];
    const float* wqs  = (const float*)d_in[6];
    const float* wqo  = (const float*)d_in[7];
    const float* wks  = (const float*)d_in[8];
    const float* wko  = (const float*)d_in[9];
    const float* wv   = (const float*)d_in[10];
    const float* fcw  = (const float*)d_in[11];
    const float* fcb  = (const float*)d_in[12];

    float* out      = (float*)d_out;
    float* attn_out = out + (size_t)B_ * L_ * V_;

    void *p_qf, *p_kf, *p_vf, *p_wqs, *p_wqo, *p_wks, *p_wko, *p_wv, *p_fcw;
    void *p_qs, *p_qo, *p_ks, *p_ko, *p_vh, *p_ctx;
    cudaGetSymbolAddress(&p_qf,  g_qf);
    cudaGetSymbolAddress(&p_kf,  g_kf);
    cudaGetSymbolAddress(&p_vf,  g_vf);
    cudaGetSymbolAddress(&p_wqs, g_wqs);
    cudaGetSymbolAddress(&p_wqo, g_wqo);
    cudaGetSymbolAddress(&p_wks, g_wks);
    cudaGetSymbolAddress(&p_wko, g_wko);
    cudaGetSymbolAddress(&p_wv,  g_wv);
    cudaGetSymbolAddress(&p_fcw, g_fcwh);
    cudaGetSymbolAddress(&p_qs,  g_qs);
    cudaGetSymbolAddress(&p_qo,  g_qo);
    cudaGetSymbolAddress(&p_ks,  g_ks);
    cudaGetSymbolAddress(&p_ko,  g_ko);
    cudaGetSymbolAddress(&p_vh,  g_vh);
    cudaGetSymbolAddress(&p_ctx, g_ctx);

    cudaFuncSetAttribute(attn_kernel,
                         cudaFuncAttributeMaxDynamicSharedMemorySize,
                         AT_SMEM_BYTES);

    // ---- prep: fp32 -> permuted fp16 ----
    Prep9 P;
    P.src[0] = q;   P.dst[0] = (__half*)p_qf;  P.n[0] = N_TOK * D_;
    P.src[1] = k;   P.dst[1] = (__half*)p_kf;  P.n[1] = N_TOK * D_;
    P.src[2] = v;   P.dst[2] = (__half*)p_vf;  P.n[2] = N_TOK * D_;
    P.src[3] = wqs; P.dst[3] = (__half*)p_wqs; P.n[3] = D_ * D_;
    P.src[4] = wqo; P.dst[4] = (__half*)p_wqo; P.n[4] = D_ * D_;
    P.src[5] = wks; P.dst[5] = (__half*)p_wks; P.n[5] = D_ * D_;
    P.src[6] = wko; P.dst[6] = (__half*)p_wko; P.n[6] = D_ * D_;
    P.src[7] = wv;  P.dst[7] = (__half*)p_wv;  P.n[7] = D_ * D_;
    P.src[8] = fcw; P.dst[8] = (__half*)p_fcw; P.n[8] = V_ * V_;
    dim3 pgrid(N_TOK * D_ / 512, 9);
    prep_kernel<<<pgrid, 256>>>(P);

    // ---- projections on fp16 tensor cores ----
    G5 g;
    g.A[0] = (const unsigned*)p_qf; g.W[0] = (const unsigned*)p_wqs;
    g.C[0] = p_qs; g.sc[0] = SCALE_F; g.md[0] = 1;
    g.A[1] = (const unsigned*)p_qf; g.W[1] = (const unsigned*)p_wqo;
    g.C[1] = p_qo; g.sc[1] = SCALE_F; g.md[1] = 1;
    g.A[2] = (const unsigned*)p_kf; g.W[2] = (const unsigned*)p_wks;
    g.C[2] = p_ks; g.sc[2] = 1.0f;   g.md[2] = 1;
    g.A[3] = (const unsigned*)p_kf; g.W[3] = (const unsigned*)p_wko;
    g.C[3] = p_ko; g.sc[3] = 1.0f;   g.md[3] = 1;
    g.A[4] = (const unsigned*)p_vf; g.W[4] = (const unsigned*)p_wv;
    g.C[4] = p_vh; g.sc[4] = 1.0f;   g.md[4] = 2;

    dim3 ggrid(2, N_TOK / 128, 5);
    proj16_kernel<<<ggrid, 256>>>(g);

    // ---- attention ----
    dim3 agrid(L_ / 32, B_);
    attn_kernel<<<agrid, 512, AT_SMEM_BYTES>>>(mask, qid, kid, attn_out);

    // ---- fc on fp16 tensor cores ----
    dim3 fgrid(2, N_TOK / 128);
    fc16_kernel<<<fgrid, 256>>>((const unsigned*)p_ctx,
                                (const unsigned*)p_fcw, out, fcb);
}

// round 13
// speedup vs baseline: 1.6148x; 1.0629x over previous
#include <cuda_runtime.h>
#include <cuda_fp16.h>
#include <math_constants.h>

#define B_  8
#define L_  1024
#define S_  1024
#define D_  256
#define V_  256
#define H_  8

#define N_TOK (B_*L_)
#define SCALE_F 0.17677669529663687f

// pair permutation for m16n8k16 fragment adjacency: p in 0..7
__host__ __device__ __forceinline__ int permp(int p)
{
    return ((p & 3) << 1) | (p >> 2);
}

// ---------------- scratch (static device arrays: allocation-free) ----------
__device__ __half g_qf[N_TOK*D_];
__device__ __half g_kf[N_TOK*D_];
__device__ __half g_vf[N_TOK*D_];
__device__ __half g_wqs[D_*D_], g_wqo[D_*D_], g_wks[D_*D_];
__device__ __half g_wko[D_*D_], g_wv[D_*D_], g_fcwh[V_*V_];

__device__ __half g_qs[N_TOK*D_];
__device__ __half g_qo[N_TOK*D_];
__device__ __half g_ks[N_TOK*D_];
__device__ __half g_ko[N_TOK*D_];
__device__ __half g_vh[N_TOK*D_];
__device__ __half g_ctx[N_TOK*V_];

// ---------------- fast exp on FMA pipe (rel err ~2e-6) ---------------------
__device__ __forceinline__ float fexp(float x)
{
    float t = fmaxf(x * 1.4426950408889634f, -125.0f);
    float r = rintf(t);
    float f = t - r;
    float p = 1.3333558146428443e-3f;
    p = fmaf(p, f, 9.6181291076284772e-3f);
    p = fmaf(p, f, 5.5504108664821580e-2f);
    p = fmaf(p, f, 2.4022650695910071e-1f);
    p = fmaf(p, f, 6.9314718055994531e-1f);
    p = fmaf(p, f, 1.0f);
    return __int_as_float(__float_as_int(p) + (((int)r) << 23));
}

__device__ __forceinline__ void mma_f16(float c[4], const unsigned a[4],
                                        const unsigned b[2])
{
    asm("mma.sync.aligned.m16n8k16.row.col.f32.f16.f16.f32 "
        "{%0,%1,%2,%3}, {%4,%5,%6,%7}, {%8,%9}, {%0,%1,%2,%3};"
        : "+f"(c[0]), "+f"(c[1]), "+f"(c[2]), "+f"(c[3])
        : "r"(a[0]), "r"(a[1]), "r"(a[2]), "r"(a[3]),
          "r"(b[0]), "r"(b[1]));
}

// ---------------------------------------------------------------------------
// Prep: fp32 -> fp16 pair-permuted (K=256 rows).
// ---------------------------------------------------------------------------
struct Prep9 {
    const float* src[9];
    __half*      dst[9];
    int          n[9];
};

__global__ __launch_bounds__(256)
void prep_kernel(Prep9 P)
{
    int z = blockIdx.y;
    int idx = blockIdx.x * 256 + threadIdx.x;
    int i2 = idx * 2;
    if (i2 >= P.n[z]) return;
    float2 v = *reinterpret_cast<const float2*>(&P.src[z][i2]);
    int c = i2 & 255;
    int pos = (c & ~15) + permp((c & 15) >> 1) * 2;
    *reinterpret_cast<__half2*>(&P.dst[z][(size_t)(i2 >> 8) * 256 + pos]) =
        __floats2half2_rn(v.x, v.y);
}

// ---------------------------------------------------------------------------
// gemm16: warp tile 32x32, block tile 128m x 64n, 256 thr, 3 blocks/SM.
// mode 0: fp32 row-major + bias | mode 1: fp16 permuted | mode 2: v blocked
// ---------------------------------------------------------------------------
__device__ __forceinline__ void gemm16_body(
    const unsigned* __restrict__ A, const unsigned* __restrict__ Bw,
    void* __restrict__ Cout, float scale, int mode,
    const float* __restrict__ bias)
{
    const int t    = threadIdx.x;
    const int w    = t >> 5;
    const int lane = t & 31;
    const int gid  = lane >> 2;
    const int tid4 = lane & 3;

    const int m0 = blockIdx.y * 128 + (w & 3) * 32;
    const int n0 = blockIdx.x * 64 + (w >> 2) * 32;

    float c[2][4][4];
#pragma unroll
    for (int rt = 0; rt < 2; rt++)
#pragma unroll
        for (int nt = 0; nt < 4; nt++)
#pragma unroll
            for (int e = 0; e < 4; e++) c[rt][nt][e] = 0.f;

#pragma unroll 4
    for (int kg = 0; kg < 16; kg++) {
        const int ko = kg * 8 + 2 * tid4;
        unsigned a[2][4];
#pragma unroll
        for (int rt = 0; rt < 2; rt++) {
            uint2 lo = *reinterpret_cast<const uint2*>(
                &A[(size_t)(m0 + rt * 16 + gid) * 128 + ko]);
            uint2 hi = *reinterpret_cast<const uint2*>(
                &A[(size_t)(m0 + rt * 16 + gid + 8) * 128 + ko]);
            a[rt][0] = lo.x; a[rt][1] = hi.x;
            a[rt][2] = lo.y; a[rt][3] = hi.y;
        }
#pragma unroll
        for (int nt = 0; nt < 4; nt++) {
            uint2 bb = *reinterpret_cast<const uint2*>(
                &Bw[(size_t)(n0 + nt * 8 + gid) * 128 + ko]);
            unsigned bfr[2] = {bb.x, bb.y};
            mma_f16(c[0][nt], a[0], bfr);
            mma_f16(c[1][nt], a[1], bfr);
        }
    }

    if (mode == 0) {
        float* Cf = (float*)Cout;
#pragma unroll
        for (int nt = 0; nt < 4; nt++) {
            int col = n0 + nt * 8 + 2 * tid4;
            float b0 = bias ? bias[col] : 0.f;
            float b1 = bias ? bias[col + 1] : 0.f;
#pragma unroll
            for (int rt = 0; rt < 2; rt++) {
                int r0 = m0 + rt * 16 + gid;
                *reinterpret_cast<float2*>(&Cf[(size_t)r0 * 256 + col]) =
                    make_float2(c[rt][nt][0] * scale + b0,
                                c[rt][nt][1] * scale + b1);
                *reinterpret_cast<float2*>(&Cf[(size_t)(r0 + 8) * 256 + col]) =
                    make_float2(c[rt][nt][2] * scale + b0,
                                c[rt][nt][3] * scale + b1);
            }
        }
    } else if (mode == 1) {
        __half* Ch = (__half*)Cout;
#pragma unroll
        for (int nt = 0; nt < 4; nt++) {
            int col = n0 + nt * 8 + 2 * tid4;
            int pos = (col & ~15) + permp((col & 15) >> 1) * 2;
#pragma unroll
            for (int rt = 0; rt < 2; rt++) {
                int r0 = m0 + rt * 16 + gid;
                *reinterpret_cast<__half2*>(&Ch[(size_t)r0 * 256 + pos]) =
                    __floats2half2_rn(c[rt][nt][0] * scale,
                                      c[rt][nt][1] * scale);
                *reinterpret_cast<__half2*>(&Ch[(size_t)(r0 + 8) * 256 + pos]) =
                    __floats2half2_rn(c[rt][nt][2] * scale,
                                      c[rt][nt][3] * scale);
            }
        }
    } else {
        __half* Ch = (__half*)Cout;
#pragma unroll
        for (int rt = 0; rt < 2; rt++)
#pragma unroll
            for (int rp = 0; rp < 2; rp++) {
                int r  = m0 + rt * 16 + gid + 8 * rp;
                int bb2 = r >> 10;
                int s  = r & 1023;
                int ph = permp((s & 15) >> 1) * 2 + (s & 1);
                size_t base0 = ((size_t)(bb2 * 64 + (s >> 4))) * 8;
#pragma unroll
                for (int nt = 0; nt < 4; nt++) {
#pragma unroll
                    for (int e = 0; e < 2; e++) {
                        int n = n0 + nt * 8 + 2 * tid4 + e;
                        size_t hi = ((base0 + (n >> 5)) * 32 + (n & 31)) * 16 + ph;
                        Ch[hi] = __float2half(c[rt][nt][2 * rp + e]);
                    }
                }
            }
    }
}

struct G5 {
    const unsigned* A[5];
    const unsigned* W[5];
    void*           C[5];
    float           sc[5];
    int             md[5];
};

__global__ __launch_bounds__(256, 3)
void proj16_kernel(G5 g)
{
    int z = blockIdx.z;
    gemm16_body(g.A[z], g.W[z], g.C[z], g.sc[z], g.md[z], nullptr);
}

__global__ __launch_bounds__(256, 3)
void fc16_kernel(const unsigned* __restrict__ A, const unsigned* __restrict__ W,
                 float* __restrict__ C, const float* __restrict__ bias)
{
    gemm16_body(A, W, C, 1.0f, 0, bias);
}

// ---------------------------------------------------------------------------
// Attention, head-paired attn_out RMW.
// smem: score [32][1036] fp32 | eh uint[32][516] | red [4][32][36]
//       inv[64] | qid 32 | kid 1024
// h1 e-values are packed fp16 in-place into the score strip:
//   unsigned stride 1036 per row, bank-skew +4 for odd (row>>2)&1,
//   max offset 519 < 1036 (in-bounds).
// ---------------------------------------------------------------------------
#define SC_STR 1036
#define EH_STR 516
#define AT_SMEM_BYTES ((32*SC_STR + 32*EH_STR + 4608 + 64 + 32 + 1024) * 4)

__device__ __forceinline__ void score_phase(
    int h, const float* __restrict__ mask, float* score,
    const int* qid_s, const int* kid_s,
    size_t qbase, size_t kbase, size_t mrow0,
    int cb, int gid, int tid4)
{
    unsigned aS[2][2][4], aO[2][2][4];
#pragma unroll
    for (int rt = 0; rt < 2; rt++) {
        const size_t r0 = (qbase + rt * 16 + gid) * D_ + h * 32;
        const size_t r1 = r0 + 8 * D_;
#pragma unroll
        for (int g = 0; g < 2; g++) {
            int off = g * 16 + 4 * tid4;
            uint2 lo = *reinterpret_cast<const uint2*>(&g_qs[r0 + off]);
            uint2 hi = *reinterpret_cast<const uint2*>(&g_qs[r1 + off]);
            aS[rt][g][0] = lo.x; aS[rt][g][1] = hi.x;
            aS[rt][g][2] = lo.y; aS[rt][g][3] = hi.y;
            lo = *reinterpret_cast<const uint2*>(&g_qo[r0 + off]);
            hi = *reinterpret_cast<const uint2*>(&g_qo[r1 + off]);
            aO[rt][g][0] = lo.x; aO[rt][g][1] = hi.x;
            aO[rt][g][2] = lo.y; aO[rt][g][3] = hi.y;
        }
    }
    int qi[2][2];
#pragma unroll
    for (int rt = 0; rt < 2; rt++) {
        qi[rt][0] = qid_s[rt * 16 + gid];
        qi[rt][1] = qid_s[rt * 16 + gid + 8];
    }

#pragma unroll 2
    for (int nt = 0; nt < 8; nt++) {
        const int sK   = cb + nt * 8 + gid;
        const int scol = cb + nt * 8 + 2 * tid4;

        unsigned bS[2][2], bO[2][2];
        const size_t krow = (kbase + sK) * D_ + h * 32;
#pragma unroll
        for (int g = 0; g < 2; g++) {
            int off = g * 16 + 4 * tid4;
            uint2 v = *reinterpret_cast<const uint2*>(&g_ks[krow + off]);
            bS[g][0] = v.x; bS[g][1] = v.y;
            v = *reinterpret_cast<const uint2*>(&g_ko[krow + off]);
            bO[g][0] = v.x; bO[g][1] = v.y;
        }

        int2 ki = *reinterpret_cast<const int2*>(&kid_s[scol]);
        float2 mf[2][2];
#pragma unroll
        for (int rt = 0; rt < 2; rt++)
#pragma unroll
            for (int rp = 0; rp < 2; rp++) {
                int row = rt * 16 + gid + 8 * rp;
                mf[rt][rp] = *reinterpret_cast<const float2*>(
                    &mask[mrow0 + (size_t)row * S_ + scol]);
            }

        float cS[2][4] = {{0,0,0,0},{0,0,0,0}};
        float cO[2][4] = {{0,0,0,0},{0,0,0,0}};
#pragma unroll
        for (int g = 0; g < 2; g++)
#pragma unroll
            for (int rt = 0; rt < 2; rt++) {
                mma_f16(cS[rt], aS[rt][g], bS[g]);
                mma_f16(cO[rt], aO[rt][g], bO[g]);
            }

#pragma unroll
        for (int rt = 0; rt < 2; rt++)
#pragma unroll
            for (int rp = 0; rp < 2; rp++) {
                int row = rt * 16 + gid + 8 * rp;
                float v0 = ((qi[rt][rp] == ki.x) ? cS[rt][2*rp]   : cO[rt][2*rp])   + mf[rt][rp].x;
                float v1 = ((qi[rt][rp] == ki.y) ? cS[rt][2*rp+1] : cO[rt][2*rp+1]) + mf[rt][rp].y;
                *reinterpret_cast<float2*>(&score[row * SC_STR + scol]) =
                    make_float2(v0, v1);
            }
    }
}

__device__ __forceinline__ void pv_phase(
    int h, const unsigned* __restrict__ ebase, int estride, bool skew,
    float* red, int b, int nc, int sh, int gid, int tid4)
{
    float cv[2][4] = {{0,0,0,0},{0,0,0,0}};
    const size_t vb0 = ((((size_t)(b * 64 + sh * 16) * 8 + h) * 32 +
                         nc * 8 + gid)) * 8 + 2 * tid4;
    const unsigned* vh_u = reinterpret_cast<const unsigned*>(g_vh);

#pragma unroll 4
    for (int kstep = 0; kstep < 16; kstep++) {
        uint2 bvv = *reinterpret_cast<const uint2*>(
            &vh_u[vb0 + (size_t)kstep * 2048]);
        unsigned bfrag[2] = {bvv.x, bvv.y};
        const int k8 = sh * 128 + kstep * 8;
#pragma unroll
        for (int rt = 0; rt < 2; rt++) {
            int row0 = rt * 16 + gid;
            int row1 = row0 + 8;
            const unsigned* e0 = ebase + row0 * estride +
                                 (skew ? (((row0 >> 2) & 1) << 2) : 0);
            const unsigned* e1 = ebase + row1 * estride +
                                 (skew ? (((row1 >> 2) & 1) << 2) : 0);
            unsigned av[4];
            av[0] = e0[k8 + tid4];
            av[1] = e1[k8 + tid4];
            av[2] = e0[k8 + tid4 + 4];
            av[3] = e1[k8 + tid4 + 4];
            mma_f16(cv[rt], av, bfrag);
        }
    }

#pragma unroll
    for (int rt = 0; rt < 2; rt++)
#pragma unroll
        for (int rp = 0; rp < 2; rp++) {
            int row = rt * 16 + gid + 8 * rp;
            *reinterpret_cast<float2*>(
                &red[sh * 1152 + row * 36 + nc * 8 + 2 * tid4]) =
                make_float2(cv[rt][2*rp], cv[rt][2*rp+1]);
        }
}

__global__ __launch_bounds__(512, 1)
void attn_kernel(const float* __restrict__ mask,
                 const int* __restrict__ qid,
                 const int* __restrict__ kid,
                 float* __restrict__ attn_out)
{
    extern __shared__ float sm[];
    float*    score = sm;                            // [32][1036] fp32
    unsigned* eh    = (unsigned*)(sm + 32 * SC_STR); // [32][516] half2
    float*    red   = sm + 32 * SC_STR + 32 * EH_STR;// [4][32][36]
    float*    inv   = red + 4608;                    // [64]
    int*      qid_s = (int*)(inv + 64);              // [32]
    int*      kid_s = qid_s + 32;                    // [1024]

    const int b    = blockIdx.y;
    const int l0   = blockIdx.x * 32;
    const int t    = threadIdx.x;
    const int lane = t & 31;
    const int w    = t >> 5;
    const int gid  = lane >> 2;
    const int tid4 = lane & 3;

    const size_t qbase = (size_t)(b * L_ + l0);
    const size_t kbase = (size_t)(b * S_);
    const size_t mrow0 = qbase * S_;

    const int cb = w * 64;
    const int nc = w & 3;
    const int sh = w >> 2;

    for (int i = t; i < S_; i += 512) kid_s[i] = kid[b * S_ + i];
    if (t < 32) qid_s[t] = qid[b * L_ + l0 + t];

    for (int ph = 0; ph < 4; ph++) {
        const int h0 = 2 * ph, h1 = h0 + 1;
        __syncthreads();   // ids visible (ph=0); strip/eh/red free (ph>0)

        // ===== head h0: score =====
        score_phase(h0, mask, score, qid_s, kid_s, qbase, kbase, mrow0,
                    cb, gid, tid4);
        __syncthreads();

        // ===== softmax h0 -> ehA (fp16), inv[row] =====
#pragma unroll
        for (int rr = 0; rr < 2; rr++) {
            int row = 2 * w + rr;
            float4* pr = (float4*)(score + row * SC_STR);
            unsigned* er = eh + row * EH_STR;
            float mx = -CUDART_INF_F;
#pragma unroll
            for (int u8 = 0; u8 < 8; u8++) {
                float4 x = pr[lane + 32 * u8];
                mx = fmaxf(mx, fmaxf(fmaxf(x.x, x.y), fmaxf(x.z, x.w)));
            }
#pragma unroll
            for (int o = 16; o > 0; o >>= 1)
                mx = fmaxf(mx, __shfl_xor_sync(0xffffffffu, mx, o));
            float s = 0.f;
#pragma unroll
            for (int u8 = 0; u8 < 8; u8++) {
                int idx = lane + 32 * u8;
                float4 x = pr[idx];
                x.x = fexp(x.x - mx); x.y = fexp(x.y - mx);
                x.z = fexp(x.z - mx); x.w = fexp(x.w - mx);
                s += (x.x + x.y) + (x.z + x.w);
                __half2 h01 = __floats2half2_rn(x.x, x.y);
                __half2 h23 = __floats2half2_rn(x.z, x.w);
                uint2 ev;
                ev.x = *reinterpret_cast<unsigned*>(&h01);
                ev.y = *reinterpret_cast<unsigned*>(&h23);
                *reinterpret_cast<uint2*>(&er[2 * idx]) = ev;
            }
#pragma unroll
            for (int o = 16; o > 0; o >>= 1)
                s += __shfl_xor_sync(0xffffffffu, s, o);
            if (lane == 0) inv[row] = 1.0f / s;
        }
        __syncthreads();

        // ===== PV h0 (reads ehA) =====
        pv_phase(h0, eh, EH_STR, false, red, b, nc, sh, gid, tid4);
        __syncthreads();

        // ===== ctx h0 + score h1 =====
        {
            int row = t >> 4;
            int d0  = (t & 15) * 2;
            float s0 = red[row * 36 + d0]        + red[1152 + row * 36 + d0] +
                       red[2304 + row * 36 + d0] + red[3456 + row * 36 + d0];
            float s1 = red[row * 36 + d0 + 1]        + red[1152 + row * 36 + d0 + 1] +
                       red[2304 + row * 36 + d0 + 1] + red[3456 + row * 36 + d0 + 1];
            float iv = inv[row];
            int n = h0 * 32 + d0;
            int pos = (n & ~15) + permp((n & 15) >> 1) * 2;
            *reinterpret_cast<__half2*>(&g_ctx[(qbase + row) * 256 + pos]) =
                __floats2half2_rn(s0 * iv, s1 * iv);
        }
        score_phase(h1, mask, score, qid_s, kid_s, qbase, kbase, mrow0,
                    cb, gid, tid4);
        __syncthreads();

        // ===== softmax h1: in-place fp16 downpack + combined RMW =====
#pragma unroll
        for (int rr = 0; rr < 2; rr++) {
            int row = 2 * w + rr;
            float4* pr = (float4*)(score + row * SC_STR);
            unsigned* eb = (unsigned*)score + row * SC_STR +
                           (((row >> 2) & 1) << 2);
            float4* out4 = reinterpret_cast<float4*>(
                attn_out + mrow0 + (size_t)row * S_);

            float mx = -CUDART_INF_F;
#pragma unroll
            for (int u8 = 0; u8 < 8; u8++) {
                float4 x = pr[lane + 32 * u8];
                mx = fmaxf(mx, fmaxf(fmaxf(x.x, x.y), fmaxf(x.z, x.w)));
            }
#pragma unroll
            for (int o = 16; o > 0; o >>= 1)
                mx = fmaxf(mx, __shfl_xor_sync(0xffffffffu, mx, o));

            float4 ov[8];
            if (ph > 0) {
#pragma unroll
                for (int u8 = 0; u8 < 8; u8++) ov[u8] = out4[lane + 32 * u8];
            }

            float s = 0.f;
#pragma unroll
            for (int u8 = 0; u8 < 8; u8++) {
                int idx = lane + 32 * u8;
                float4 x = pr[idx];
                x.x = fexp(x.x - mx); x.y = fexp(x.y - mx);
                x.z = fexp(x.z - mx); x.w = fexp(x.w - mx);
                s += (x.x + x.y) + (x.z + x.w);
                __half2 h01 = __floats2half2_rn(x.x, x.y);
                __half2 h23 = __floats2half2_rn(x.z, x.w);
                uint2 ev;
                ev.x = *reinterpret_cast<unsigned*>(&h01);
                ev.y = *reinterpret_cast<unsigned*>(&h23);
                *reinterpret_cast<uint2*>(&eb[2 * idx]) = ev;
            }
#pragma unroll
            for (int o = 16; o > 0; o >>= 1)
                s += __shfl_xor_sync(0xffffffffu, s, o);
            float iv1 = 1.0f / s;
            if (lane == 0) inv[32 + row] = iv1;

            float sv0 = inv[row] * 0.125f;
            float sv1 = iv1 * 0.125f;
            const uint2* eA2 = reinterpret_cast<const uint2*>(eh + row * EH_STR);
#pragma unroll
            for (int u8 = 0; u8 < 8; u8++) {
                int idx = lane + 32 * u8;
                uint2 a2 = eA2[idx];
                uint2 b2 = *reinterpret_cast<const uint2*>(&eb[2 * idx]);
                float2 a01 = __half22float2(*reinterpret_cast<__half2*>(&a2.x));
                float2 a23 = __half22float2(*reinterpret_cast<__half2*>(&a2.y));
                float2 b01 = __half22float2(*reinterpret_cast<__half2*>(&b2.x));
                float2 b23 = __half22float2(*reinterpret_cast<__half2*>(&b2.y));
                float4 o;
                if (ph == 0) {
                    o.x = a01.x * sv0 + b01.x * sv1;
                    o.y = a01.y * sv0 + b01.y * sv1;
                    o.z = a23.x * sv0 + b23.x * sv1;
                    o.w = a23.y * sv0 + b23.y * sv1;
                } else {
                    o.x = fmaf(a01.x, sv0, fmaf(b01.x, sv1, ov[u8].x));
                    o.y = fmaf(a01.y, sv0, fmaf(b01.y, sv1, ov[u8].y));
                    o.z = fmaf(a23.x, sv0, fmaf(b23.x, sv1, ov[u8].z));
                    o.w = fmaf(a23.y, sv0, fmaf(b23.y, sv1, ov[u8].w));
                }
                out4[idx] = o;
            }
        }
        __syncthreads();

        // ===== PV h1 (reads packed e in score strip, unsigned stride 1036) ==
        pv_phase(h1, (const unsigned*)score, SC_STR, true,
                 red, b, nc, sh, gid, tid4);
        __syncthreads();

        // ===== ctx h1 =====
        {
            int row = t >> 4;
            int d0  = (t & 15) * 2;
            float s0 = red[row * 36 + d0]        + red[1152 + row * 36 + d0] +
                       red[2304 + row * 36 + d0] + red[3456 + row * 36 + d0];
            float s1 = red[row * 36 + d0 + 1]        + red[1152 + row * 36 + d0 + 1] +
                       red[2304 + row * 36 + d0 + 1] + red[3456 + row * 36 + d0 + 1];
            float iv = inv[32 + row];
            int n = h1 * 32 + d0;
            int pos = (n & ~15) + permp((n & 15) >> 1) * 2;
            *reinterpret_cast<__half2*>(&g_ctx[(qbase + row) * 256 + pos]) =
                __floats2half2_rn(s0 * iv, s1 * iv);
        }
    }
}

// ---------------------------------------------------------------------------
extern "C" void kernel_launch(void* const* d_in, const int* in_sizes, int n_in,
                              void* d_out, int out_size)
{
    const float* q    = (const float*)d_in[0];
    const float* k    = (const float*)d_in[1];
    const float* v    = (const float*)d_in[2];
    const int*   qid  = (const int*)d_in[3];
    const int*   kid  = (const int*)d_in[4];
    const float* mask = (const float*)d_in[5];
    const float* wqs  = (const float*)d_in[6];
    const float* wqo  = (const float*)d_in[7];
    const float* wks  = (const float*)d_in[8];
    const float* wko  = (const float*)d_in[9];
    const float* wv   = (const float*)d_in[10];
    const float* fcw  = (const float*)d_in[11];
    const float* fcb  = (const float*)d_in[12];

    float* out      = (float*)d_out;
    float* attn_out = out + (size_t)B_ * L_ * V_;

    void *p_qf, *p_kf, *p_vf, *p_wqs, *p_wqo, *p_wks, *p_wko, *p_wv, *p_fcw;
    void *p_qs, *p_qo, *p_ks, *p_ko, *p_vh, *p_ctx;
    cudaGetSymbolAddress(&p_qf,  g_qf);
    cudaGetSymbolAddress(&p_kf,  g_kf);
    cudaGetSymbolAddress(&p_vf,  g_vf);
    cudaGetSymbolAddress(&p_wqs, g_wqs);
    cudaGetSymbolAddress(&p_wqo, g_wqo);
    cudaGetSymbolAddress(&p_wks, g_wks);
    cudaGetSymbolAddress(&p_wko, g_wko);
    cudaGetSymbolAddress(&p_wv,  g_wv);
    cudaGetSymbolAddress(&p_fcw, g_fcwh);
    cudaGetSymbolAddress(&p_qs,  g_qs);
    cudaGetSymbolAddress(&p_qo,  g_qo);
    cudaGetSymbolAddress(&p_ks,  g_ks);
    cudaGetSymbolAddress(&p_ko,  g_ko);
    cudaGetSymbolAddress(&p_vh,  g_vh);
    cudaGetSymbolAddress(&p_ctx, g_ctx);

    cudaFuncSetAttribute(attn_kernel,
                         cudaFuncAttributeMaxDynamicSharedMemorySize,
                         AT_SMEM_BYTES);

    Prep9 P;
    P.src[0] = q;   P.dst[0] = (__half*)p_qf;  P.n[0] = N_TOK * D_;
    P.src[1] = k;   P.dst[1] = (__half*)p_kf;  P.n[1] = N_TOK * D_;
    P.src[2] = v;   P.dst[2] = (__half*)p_vf;  P.n[2] = N_TOK * D_;
    P.src[3] = wqs; P.dst[3] = (__half*)p_wqs; P.n[3] = D_ * D_;
    P.src[4] = wqo; P.dst[4] = (__half*)p_wqo; P.n[4] = D_ * D_;
    P.src[5] = wks; P.dst[5] = (__half*)p_wks; P.n[5] = D_ * D_;
    P.src[6] = wko; P.dst[6] = (__half*)p_wko; P.n[6] = D_ * D_;
    P.src[7] = wv;  P.dst[7] = (__half*)p_wv;  P.n[7] = D_ * D_;
    P.src[8] = fcw; P.dst[8] = (__half*)p_fcw; P.n[8] = V_ * V_;
    dim3 pgrid(N_TOK * D_ / 512, 9);
    prep_kernel<<<pgrid, 256>>>(P);

    G5 g;
    g.A[0] = (const unsigned*)p_qf; g.W[0] = (const unsigned*)p_wqs;
    g.C[0] = p_qs; g.sc[0] = SCALE_F; g.md[0] = 1;
    g.A[1] = (const unsigned*)p_qf; g.W[1] = (const unsigned*)p_wqo;
    g.C[1] = p_qo; g.sc[1] = SCALE_F; g.md[1] = 1;
    g.A[2] = (const unsigned*)p_kf; g.W[2] = (const unsigned*)p_wks;
    g.C[2] = p_ks; g.sc[2] = 1.0f;   g.md[2] = 1;
    g.A[3] = (const unsigned*)p_kf; g.W[3] = (const unsigned*)p_wko;
    g.C[3] = p_ko; g.sc[3] = 1.0f;   g.md[3] = 1;
    g.A[4] = (const unsigned*)p_vf; g.W[4] = (const unsigned*)p_wv;
    g.C[4] = p_vh; g.sc[4] = 1.0f;   g.md[4] = 2;

    dim3 ggrid(4, N_TOK / 128, 5);
    proj16_kernel<<<ggrid, 256>>>(g);

    dim3 agrid(L_ / 32, B_);
    attn_kernel<<<agrid, 512, AT_SMEM_BYTES>>>(mask, qid, kid, attn_out);

    dim3 fgrid(4, N_TOK / 128);
    fc16_kernel<<<fgrid, 256>>>((const unsigned*)p_ctx,
                                (const unsigned*)p_fcw, out, fcb);
}

// round 14
// speedup vs baseline: 1.7466x; 1.0817x over previous
#include <cuda_runtime.h>
#include <cuda_fp16.h>
#include <math_constants.h>

#define B_  8
#define L_  1024
#define S_  1024
#define D_  256
#define V_  256
#define H_  8

#define N_TOK (B_*L_)
#define SCALE_F 0.17677669529663687f
#define LOG2E_F 1.4426950408889634f

// pair permutation for m16n8k16 fragment adjacency: p in 0..7
__host__ __device__ __forceinline__ int permp(int p)
{
    return ((p & 3) << 1) | (p >> 2);
}

// ---------------- scratch (static device arrays: allocation-free) ----------
__device__ __half g_qf[N_TOK*D_];
__device__ __half g_kf[N_TOK*D_];
__device__ __half g_vf[N_TOK*D_];
__device__ __half g_wqs[D_*D_], g_wqo[D_*D_], g_wks[D_*D_];
__device__ __half g_wko[D_*D_], g_wv[D_*D_], g_fcwh[V_*V_];

__device__ __half g_qs[N_TOK*D_];
__device__ __half g_qo[N_TOK*D_];
__device__ __half g_ks[N_TOK*D_];
__device__ __half g_ko[N_TOK*D_];
__device__ __half g_vh[N_TOK*D_];
__device__ __half g_ctx[N_TOK*V_];

// ---------------- exp2 on the MUFU pipe -------------------------------------
__device__ __forceinline__ float ex2f(float x)
{
    float r;
    asm("ex2.approx.ftz.f32 %0, %1;" : "=f"(r) : "f"(x));
    return r;
}

__device__ __forceinline__ void mma_f16(float c[4], const unsigned a[4],
                                        const unsigned b[2])
{
    asm("mma.sync.aligned.m16n8k16.row.col.f32.f16.f16.f32 "
        "{%0,%1,%2,%3}, {%4,%5,%6,%7}, {%8,%9}, {%0,%1,%2,%3};"
        : "+f"(c[0]), "+f"(c[1]), "+f"(c[2]), "+f"(c[3])
        : "r"(a[0]), "r"(a[1]), "r"(a[2]), "r"(a[3]),
          "r"(b[0]), "r"(b[1]));
}

// ---------------------------------------------------------------------------
// Prep: fp32 -> fp16 pair-permuted (K=256 rows).
// ---------------------------------------------------------------------------
struct Prep9 {
    const float* src[9];
    __half*      dst[9];
    int          n[9];
};

__global__ __launch_bounds__(256)
void prep_kernel(Prep9 P)
{
    int z = blockIdx.y;
    int idx = blockIdx.x * 256 + threadIdx.x;
    int i2 = idx * 2;
    if (i2 >= P.n[z]) return;
    float2 v = *reinterpret_cast<const float2*>(&P.src[z][i2]);
    int c = i2 & 255;
    int pos = (c & ~15) + permp((c & 15) >> 1) * 2;
    *reinterpret_cast<__half2*>(&P.dst[z][(size_t)(i2 >> 8) * 256 + pos]) =
        __floats2half2_rn(v.x, v.y);
}

// ---------------------------------------------------------------------------
// gemm16: warp tile 32x32, block tile 128m x 64n, 256 thr, 3 blocks/SM.
// mode 0: fp32 row-major + bias | mode 1: fp16 permuted | mode 2: v blocked
// ---------------------------------------------------------------------------
__device__ __forceinline__ void gemm16_body(
    const unsigned* __restrict__ A, const unsigned* __restrict__ Bw,
    void* __restrict__ Cout, float scale, int mode,
    const float* __restrict__ bias)
{
    const int t    = threadIdx.x;
    const int w    = t >> 5;
    const int lane = t & 31;
    const int gid  = lane >> 2;
    const int tid4 = lane & 3;

    const int m0 = blockIdx.y * 128 + (w & 3) * 32;
    const int n0 = blockIdx.x * 64 + (w >> 2) * 32;

    float c[2][4][4];
#pragma unroll
    for (int rt = 0; rt < 2; rt++)
#pragma unroll
        for (int nt = 0; nt < 4; nt++)
#pragma unroll
            for (int e = 0; e < 4; e++) c[rt][nt][e] = 0.f;

#pragma unroll 4
    for (int kg = 0; kg < 16; kg++) {
        const int ko = kg * 8 + 2 * tid4;
        unsigned a[2][4];
#pragma unroll
        for (int rt = 0; rt < 2; rt++) {
            uint2 lo = *reinterpret_cast<const uint2*>(
                &A[(size_t)(m0 + rt * 16 + gid) * 128 + ko]);
            uint2 hi = *reinterpret_cast<const uint2*>(
                &A[(size_t)(m0 + rt * 16 + gid + 8) * 128 + ko]);
            a[rt][0] = lo.x; a[rt][1] = hi.x;
            a[rt][2] = lo.y; a[rt][3] = hi.y;
        }
#pragma unroll
        for (int nt = 0; nt < 4; nt++) {
            uint2 bb = *reinterpret_cast<const uint2*>(
                &Bw[(size_t)(n0 + nt * 8 + gid) * 128 + ko]);
            unsigned bfr[2] = {bb.x, bb.y};
            mma_f16(c[0][nt], a[0], bfr);
            mma_f16(c[1][nt], a[1], bfr);
        }
    }

    if (mode == 0) {
        float* Cf = (float*)Cout;
#pragma unroll
        for (int nt = 0; nt < 4; nt++) {
            int col = n0 + nt * 8 + 2 * tid4;
            float b0 = bias ? bias[col] : 0.f;
            float b1 = bias ? bias[col + 1] : 0.f;
#pragma unroll
            for (int rt = 0; rt < 2; rt++) {
                int r0 = m0 + rt * 16 + gid;
                *reinterpret_cast<float2*>(&Cf[(size_t)r0 * 256 + col]) =
                    make_float2(c[rt][nt][0] * scale + b0,
                                c[rt][nt][1] * scale + b1);
                *reinterpret_cast<float2*>(&Cf[(size_t)(r0 + 8) * 256 + col]) =
                    make_float2(c[rt][nt][2] * scale + b0,
                                c[rt][nt][3] * scale + b1);
            }
        }
    } else if (mode == 1) {
        __half* Ch = (__half*)Cout;
#pragma unroll
        for (int nt = 0; nt < 4; nt++) {
            int col = n0 + nt * 8 + 2 * tid4;
            int pos = (col & ~15) + permp((col & 15) >> 1) * 2;
#pragma unroll
            for (int rt = 0; rt < 2; rt++) {
                int r0 = m0 + rt * 16 + gid;
                *reinterpret_cast<__half2*>(&Ch[(size_t)r0 * 256 + pos]) =
                    __floats2half2_rn(c[rt][nt][0] * scale,
                                      c[rt][nt][1] * scale);
                *reinterpret_cast<__half2*>(&Ch[(size_t)(r0 + 8) * 256 + pos]) =
                    __floats2half2_rn(c[rt][nt][2] * scale,
                                      c[rt][nt][3] * scale);
            }
        }
    } else {
        __half* Ch = (__half*)Cout;
#pragma unroll
        for (int rt = 0; rt < 2; rt++)
#pragma unroll
            for (int rp = 0; rp < 2; rp++) {
                int r  = m0 + rt * 16 + gid + 8 * rp;
                int bb2 = r >> 10;
                int s  = r & 1023;
                int ph = permp((s & 15) >> 1) * 2 + (s & 1);
                size_t base0 = ((size_t)(bb2 * 64 + (s >> 4))) * 8;
#pragma unroll
                for (int nt = 0; nt < 4; nt++) {
#pragma unroll
                    for (int e = 0; e < 2; e++) {
                        int n = n0 + nt * 8 + 2 * tid4 + e;
                        size_t hi = ((base0 + (n >> 5)) * 32 + (n & 31)) * 16 + ph;
                        Ch[hi] = __float2half(c[rt][nt][2 * rp + e]);
                    }
                }
            }
    }
}

struct G5 {
    const unsigned* A[5];
    const unsigned* W[5];
    void*           C[5];
    float           sc[5];
    int             md[5];
};

__global__ __launch_bounds__(256, 3)
void proj16_kernel(G5 g)
{
    int z = blockIdx.z;
    gemm16_body(g.A[z], g.W[z], g.C[z], g.sc[z], g.md[z], nullptr);
}

__global__ __launch_bounds__(256, 3)
void fc16_kernel(const unsigned* __restrict__ A, const unsigned* __restrict__ W,
                 float* __restrict__ C, const float* __restrict__ bias)
{
    gemm16_body(A, W, C, 1.0f, 0, bias);
}

// ---------------------------------------------------------------------------
// Attention, head-paired attn_out RMW, log2-domain scores + MUFU EX2 softmax.
// smem: score [32][1036] fp32 | eh uint[32][516] | red [4][32][36]
//       inv[64] | qid 32 | kid 1024
// ---------------------------------------------------------------------------
#define SC_STR 1036
#define EH_STR 516
#define AT_SMEM_BYTES ((32*SC_STR + 32*EH_STR + 4608 + 64 + 32 + 1024) * 4)

__device__ __forceinline__ void score_phase(
    int h, const float* __restrict__ mask, float* score,
    const int* qid_s, const int* kid_s,
    size_t qbase, size_t kbase, size_t mrow0,
    int cb, int gid, int tid4)
{
    unsigned aS[2][2][4], aO[2][2][4];
#pragma unroll
    for (int rt = 0; rt < 2; rt++) {
        const size_t r0 = (qbase + rt * 16 + gid) * D_ + h * 32;
        const size_t r1 = r0 + 8 * D_;
#pragma unroll
        for (int g = 0; g < 2; g++) {
            int off = g * 16 + 4 * tid4;
            uint2 lo = *reinterpret_cast<const uint2*>(&g_qs[r0 + off]);
            uint2 hi = *reinterpret_cast<const uint2*>(&g_qs[r1 + off]);
            aS[rt][g][0] = lo.x; aS[rt][g][1] = hi.x;
            aS[rt][g][2] = lo.y; aS[rt][g][3] = hi.y;
            lo = *reinterpret_cast<const uint2*>(&g_qo[r0 + off]);
            hi = *reinterpret_cast<const uint2*>(&g_qo[r1 + off]);
            aO[rt][g][0] = lo.x; aO[rt][g][1] = hi.x;
            aO[rt][g][2] = lo.y; aO[rt][g][3] = hi.y;
        }
    }
    int qi[2][2];
#pragma unroll
    for (int rt = 0; rt < 2; rt++) {
        qi[rt][0] = qid_s[rt * 16 + gid];
        qi[rt][1] = qid_s[rt * 16 + gid + 8];
    }

#pragma unroll 2
    for (int nt = 0; nt < 8; nt++) {
        const int sK   = cb + nt * 8 + gid;
        const int scol = cb + nt * 8 + 2 * tid4;

        unsigned bS[2][2], bO[2][2];
        const size_t krow = (kbase + sK) * D_ + h * 32;
#pragma unroll
        for (int g = 0; g < 2; g++) {
            int off = g * 16 + 4 * tid4;
            uint2 v = *reinterpret_cast<const uint2*>(&g_ks[krow + off]);
            bS[g][0] = v.x; bS[g][1] = v.y;
            v = *reinterpret_cast<const uint2*>(&g_ko[krow + off]);
            bO[g][0] = v.x; bO[g][1] = v.y;
        }

        int2 ki = *reinterpret_cast<const int2*>(&kid_s[scol]);
        float2 mf[2][2];
#pragma unroll
        for (int rt = 0; rt < 2; rt++)
#pragma unroll
            for (int rp = 0; rp < 2; rp++) {
                int row = rt * 16 + gid + 8 * rp;
                mf[rt][rp] = *reinterpret_cast<const float2*>(
                    &mask[mrow0 + (size_t)row * S_ + scol]);
            }

        float cS[2][4] = {{0,0,0,0},{0,0,0,0}};
        float cO[2][4] = {{0,0,0,0},{0,0,0,0}};
#pragma unroll
        for (int g = 0; g < 2; g++)
#pragma unroll
            for (int rt = 0; rt < 2; rt++) {
                mma_f16(cS[rt], aS[rt][g], bS[g]);
                mma_f16(cO[rt], aO[rt][g], bO[g]);
            }

        // scores are in log2 domain (q pre-scaled by SCALE*log2e);
        // mask folded in log2 domain via FMA by LOG2E.
#pragma unroll
        for (int rt = 0; rt < 2; rt++)
#pragma unroll
            for (int rp = 0; rp < 2; rp++) {
                int row = rt * 16 + gid + 8 * rp;
                float s0 = (qi[rt][rp] == ki.x) ? cS[rt][2*rp]   : cO[rt][2*rp];
                float s1 = (qi[rt][rp] == ki.y) ? cS[rt][2*rp+1] : cO[rt][2*rp+1];
                float v0 = fmaf(mf[rt][rp].x, LOG2E_F, s0);
                float v1 = fmaf(mf[rt][rp].y, LOG2E_F, s1);
                *reinterpret_cast<float2*>(&score[row * SC_STR + scol]) =
                    make_float2(v0, v1);
            }
    }
}

__device__ __forceinline__ void pv_phase(
    int h, const unsigned* __restrict__ ebase, int estride, bool skew,
    float* red, int b, int nc, int sh, int gid, int tid4)
{
    float cv[2][4] = {{0,0,0,0},{0,0,0,0}};
    const size_t vb0 = ((((size_t)(b * 64 + sh * 16) * 8 + h) * 32 +
                         nc * 8 + gid)) * 8 + 2 * tid4;
    const unsigned* vh_u = reinterpret_cast<const unsigned*>(g_vh);

#pragma unroll 4
    for (int kstep = 0; kstep < 16; kstep++) {
        uint2 bvv = *reinterpret_cast<const uint2*>(
            &vh_u[vb0 + (size_t)kstep * 2048]);
        unsigned bfrag[2] = {bvv.x, bvv.y};
        const int k8 = sh * 128 + kstep * 8;
#pragma unroll
        for (int rt = 0; rt < 2; rt++) {
            int row0 = rt * 16 + gid;
            int row1 = row0 + 8;
            const unsigned* e0 = ebase + row0 * estride +
                                 (skew ? (((row0 >> 2) & 1) << 2) : 0);
            const unsigned* e1 = ebase + row1 * estride +
                                 (skew ? (((row1 >> 2) & 1) << 2) : 0);
            unsigned av[4];
            av[0] = e0[k8 + tid4];
            av[1] = e1[k8 + tid4];
            av[2] = e0[k8 + tid4 + 4];
            av[3] = e1[k8 + tid4 + 4];
            mma_f16(cv[rt], av, bfrag);
        }
    }

#pragma unroll
    for (int rt = 0; rt < 2; rt++)
#pragma unroll
        for (int rp = 0; rp < 2; rp++) {
            int row = rt * 16 + gid + 8 * rp;
            *reinterpret_cast<float2*>(
                &red[sh * 1152 + row * 36 + nc * 8 + 2 * tid4]) =
                make_float2(cv[rt][2*rp], cv[rt][2*rp+1]);
        }
}

__global__ __launch_bounds__(512, 1)
void attn_kernel(const float* __restrict__ mask,
                 const int* __restrict__ qid,
                 const int* __restrict__ kid,
                 float* __restrict__ attn_out)
{
    extern __shared__ float sm[];
    float*    score = sm;                            // [32][1036] fp32
    unsigned* eh    = (unsigned*)(sm + 32 * SC_STR); // [32][516] half2
    float*    red   = sm + 32 * SC_STR + 32 * EH_STR;// [4][32][36]
    float*    inv   = red + 4608;                    // [64]
    int*      qid_s = (int*)(inv + 64);              // [32]
    int*      kid_s = qid_s + 32;                    // [1024]

    const int b    = blockIdx.y;
    const int l0   = blockIdx.x * 32;
    const int t    = threadIdx.x;
    const int lane = t & 31;
    const int w    = t >> 5;
    const int gid  = lane >> 2;
    const int tid4 = lane & 3;

    const size_t qbase = (size_t)(b * L_ + l0);
    const size_t kbase = (size_t)(b * S_);
    const size_t mrow0 = qbase * S_;

    const int cb = w * 64;
    const int nc = w & 3;
    const int sh = w >> 2;

    for (int i = t; i < S_; i += 512) kid_s[i] = kid[b * S_ + i];
    if (t < 32) qid_s[t] = qid[b * L_ + l0 + t];

    for (int ph = 0; ph < 4; ph++) {
        const int h0 = 2 * ph, h1 = h0 + 1;
        __syncthreads();   // ids visible (ph=0); strip/eh/red free (ph>0)

        // ===== head h0: score =====
        score_phase(h0, mask, score, qid_s, kid_s, qbase, kbase, mrow0,
                    cb, gid, tid4);
        __syncthreads();

        // ===== softmax h0 -> ehA (fp16), inv[row] =====
#pragma unroll
        for (int rr = 0; rr < 2; rr++) {
            int row = 2 * w + rr;
            float4* pr = (float4*)(score + row * SC_STR);
            unsigned* er = eh + row * EH_STR;
            float mx = -CUDART_INF_F;
#pragma unroll
            for (int u8 = 0; u8 < 8; u8++) {
                float4 x = pr[lane + 32 * u8];
                mx = fmaxf(mx, fmaxf(fmaxf(x.x, x.y), fmaxf(x.z, x.w)));
            }
#pragma unroll
            for (int o = 16; o > 0; o >>= 1)
                mx = fmaxf(mx, __shfl_xor_sync(0xffffffffu, mx, o));
            float s = 0.f;
#pragma unroll
            for (int u8 = 0; u8 < 8; u8++) {
                int idx = lane + 32 * u8;
                float4 x = pr[idx];
                x.x = ex2f(x.x - mx); x.y = ex2f(x.y - mx);
                x.z = ex2f(x.z - mx); x.w = ex2f(x.w - mx);
                s += (x.x + x.y) + (x.z + x.w);
                __half2 h01 = __floats2half2_rn(x.x, x.y);
                __half2 h23 = __floats2half2_rn(x.z, x.w);
                uint2 ev;
                ev.x = *reinterpret_cast<unsigned*>(&h01);
                ev.y = *reinterpret_cast<unsigned*>(&h23);
                *reinterpret_cast<uint2*>(&er[2 * idx]) = ev;
            }
#pragma unroll
            for (int o = 16; o > 0; o >>= 1)
                s += __shfl_xor_sync(0xffffffffu, s, o);
            if (lane == 0) inv[row] = 1.0f / s;
        }
        __syncthreads();

        // ===== PV h0 (reads ehA) =====
        pv_phase(h0, eh, EH_STR, false, red, b, nc, sh, gid, tid4);
        __syncthreads();

        // ===== ctx h0 + score h1 =====
        {
            int row = t >> 4;
            int d0  = (t & 15) * 2;
            float s0 = red[row * 36 + d0]        + red[1152 + row * 36 + d0] +
                       red[2304 + row * 36 + d0] + red[3456 + row * 36 + d0];
            float s1 = red[row * 36 + d0 + 1]        + red[1152 + row * 36 + d0 + 1] +
                       red[2304 + row * 36 + d0 + 1] + red[3456 + row * 36 + d0 + 1];
            float iv = inv[row];
            int n = h0 * 32 + d0;
            int pos = (n & ~15) + permp((n & 15) >> 1) * 2;
            *reinterpret_cast<__half2*>(&g_ctx[(qbase + row) * 256 + pos]) =
                __floats2half2_rn(s0 * iv, s1 * iv);
        }
        score_phase(h1, mask, score, qid_s, kid_s, qbase, kbase, mrow0,
                    cb, gid, tid4);
        __syncthreads();

        // ===== softmax h1: in-place fp16 downpack + combined RMW =====
#pragma unroll
        for (int rr = 0; rr < 2; rr++) {
            int row = 2 * w + rr;
            float4* pr = (float4*)(score + row * SC_STR);
            unsigned* eb = (unsigned*)score + row * SC_STR +
                           (((row >> 2) & 1) << 2);
            float4* out4 = reinterpret_cast<float4*>(
                attn_out + mrow0 + (size_t)row * S_);

            float mx = -CUDART_INF_F;
#pragma unroll
            for (int u8 = 0; u8 < 8; u8++) {
                float4 x = pr[lane + 32 * u8];
                mx = fmaxf(mx, fmaxf(fmaxf(x.x, x.y), fmaxf(x.z, x.w)));
            }
#pragma unroll
            for (int o = 16; o > 0; o >>= 1)
                mx = fmaxf(mx, __shfl_xor_sync(0xffffffffu, mx, o));

            float4 ov[8];
            if (ph > 0) {
#pragma unroll
                for (int u8 = 0; u8 < 8; u8++) ov[u8] = out4[lane + 32 * u8];
            }

            float s = 0.f;
#pragma unroll
            for (int u8 = 0; u8 < 8; u8++) {
                int idx = lane + 32 * u8;
                float4 x = pr[idx];
                x.x = ex2f(x.x - mx); x.y = ex2f(x.y - mx);
                x.z = ex2f(x.z - mx); x.w = ex2f(x.w - mx);
                s += (x.x + x.y) + (x.z + x.w);
                __half2 h01 = __floats2half2_rn(x.x, x.y);
                __half2 h23 = __floats2half2_rn(x.z, x.w);
                uint2 ev;
                ev.x = *reinterpret_cast<unsigned*>(&h01);
                ev.y = *reinterpret_cast<unsigned*>(&h23);
                *reinterpret_cast<uint2*>(&eb[2 * idx]) = ev;
            }
#pragma unroll
            for (int o = 16; o > 0; o >>= 1)
                s += __shfl_xor_sync(0xffffffffu, s, o);
            float iv1 = 1.0f / s;
            if (lane == 0) inv[32 + row] = iv1;

            float sv0 = inv[row] * 0.125f;
            float sv1 = iv1 * 0.125f;
            const uint2* eA2 = reinterpret_cast<const uint2*>(eh + row * EH_STR);
#pragma unroll
            for (int u8 = 0; u8 < 8; u8++) {
                int idx = lane + 32 * u8;
                uint2 a2 = eA2[idx];
                uint2 b2 = *reinterpret_cast<const uint2*>(&eb[2 * idx]);
                float2 a01 = __half22float2(*reinterpret_cast<__half2*>(&a2.x));
                float2 a23 = __half22float2(*reinterpret_cast<__half2*>(&a2.y));
                float2 b01 = __half22float2(*reinterpret_cast<__half2*>(&b2.x));
                float2 b23 = __half22float2(*reinterpret_cast<__half2*>(&b2.y));
                float4 o;
                if (ph == 0) {
                    o.x = a01.x * sv0 + b01.x * sv1;
                    o.y = a01.y * sv0 + b01.y * sv1;
                    o.z = a23.x * sv0 + b23.x * sv1;
                    o.w = a23.y * sv0 + b23.y * sv1;
                } else {
                    o.x = fmaf(a01.x, sv0, fmaf(b01.x, sv1, ov[u8].x));
                    o.y = fmaf(a01.y, sv0, fmaf(b01.y, sv1, ov[u8].y));
                    o.z = fmaf(a23.x, sv0, fmaf(b23.x, sv1, ov[u8].z));
                    o.w = fmaf(a23.y, sv0, fmaf(b23.y, sv1, ov[u8].w));
                }
                out4[idx] = o;
            }
        }
        __syncthreads();

        // ===== PV h1 (reads packed e in score strip, unsigned stride 1036) ==
        pv_phase(h1, (const unsigned*)score, SC_STR, true,
                 red, b, nc, sh, gid, tid4);
        __syncthreads();

        // ===== ctx h1 =====
        {
            int row = t >> 4;
            int d0  = (t & 15) * 2;
            float s0 = red[row * 36 + d0]        + red[1152 + row * 36 + d0] +
                       red[2304 + row * 36 + d0] + red[3456 + row * 36 + d0];
            float s1 = red[row * 36 + d0 + 1]        + red[1152 + row * 36 + d0 + 1] +
                       red[2304 + row * 36 + d0 + 1] + red[3456 + row * 36 + d0 + 1];
            float iv = inv[32 + row];
            int n = h1 * 32 + d0;
            int pos = (n & ~15) + permp((n & 15) >> 1) * 2;
            *reinterpret_cast<__half2*>(&g_ctx[(qbase + row) * 256 + pos]) =
                __floats2half2_rn(s0 * iv, s1 * iv);
        }
    }
}

// ---------------------------------------------------------------------------
extern "C" void kernel_launch(void* const* d_in, const int* in_sizes, int n_in,
                              void* d_out, int out_size)
{
    const float* q    = (const float*)d_in[0];
    const float* k    = (const float*)d_in[1];
    const float* v    = (const float*)d_in[2];
    const int*   qid  = (const int*)d_in[3];
    const int*   kid  = (const int*)d_in[4];
    const float* mask = (const float*)d_in[5];
    const float* wqs  = (const float*)d_in[6];
    const float* wqo  = (const float*)d_in[7];
    const float* wks  = (const float*)d_in[8];
    const float* wko  = (const float*)d_in[9];
    const float* wv   = (const float*)d_in[10];
    const float* fcw  = (const float*)d_in[11];
    const float* fcb  = (const float*)d_in[12];

    float* out      = (float*)d_out;
    float* attn_out = out + (size_t)B_ * L_ * V_;

    void *p_qf, *p_kf, *p_vf, *p_wqs, *p_wqo, *p_wks, *p_wko, *p_wv, *p_fcw;
    void *p_qs, *p_qo, *p_ks, *p_ko, *p_vh, *p_ctx;
    cudaGetSymbolAddress(&p_qf,  g_qf);
    cudaGetSymbolAddress(&p_kf,  g_kf);
    cudaGetSymbolAddress(&p_vf,  g_vf);
    cudaGetSymbolAddress(&p_wqs, g_wqs);
    cudaGetSymbolAddress(&p_wqo, g_wqo);
    cudaGetSymbolAddress(&p_wks, g_wks);
    cudaGetSymbolAddress(&p_wko, g_wko);
    cudaGetSymbolAddress(&p_wv,  g_wv);
    cudaGetSymbolAddress(&p_fcw, g_fcwh);
    cudaGetSymbolAddress(&p_qs,  g_qs);
    cudaGetSymbolAddress(&p_qo,  g_qo);
    cudaGetSymbolAddress(&p_ks,  g_ks);
    cudaGetSymbolAddress(&p_ko,  g_ko);
    cudaGetSymbolAddress(&p_vh,  g_vh);
    cudaGetSymbolAddress(&p_ctx, g_ctx);

    cudaFuncSetAttribute(attn_kernel,
                         cudaFuncAttributeMaxDynamicSharedMemorySize,
                         AT_SMEM_BYTES);

    Prep9 P;
    P.src[0] = q;   P.dst[0] = (__half*)p_qf;  P.n[0] = N_TOK * D_;
    P.src[1] = k;   P.dst[1] = (__half*)p_kf;  P.n[1] = N_TOK * D_;
    P.src[2] = v;   P.dst[2] = (__half*)p_vf;  P.n[2] = N_TOK * D_;
    P.src[3] = wqs; P.dst[3] = (__half*)p_wqs; P.n[3] = D_ * D_;
    P.src[4] = wqo; P.dst[4] = (__half*)p_wqo; P.n[4] = D_ * D_;
    P.src[5] = wks; P.dst[5] = (__half*)p_wks; P.n[5] = D_ * D_;
    P.src[6] = wko; P.dst[6] = (__half*)p_wko; P.n[6] = D_ * D_;
    P.src[7] = wv;  P.dst[7] = (__half*)p_wv;  P.n[7] = D_ * D_;
    P.src[8] = fcw; P.dst[8] = (__half*)p_fcw; P.n[8] = V_ * V_;
    dim3 pgrid(N_TOK * D_ / 512, 9);
    prep_kernel<<<pgrid, 256>>>(P);

    // q projections pre-scaled by SCALE*log2e -> scores in log2 domain
    G5 g;
    g.A[0] = (const unsigned*)p_qf; g.W[0] = (const unsigned*)p_wqs;
    g.C[0] = p_qs; g.sc[0] = SCALE_F * LOG2E_F; g.md[0] = 1;
    g.A[1] = (const unsigned*)p_qf; g.W[1] = (const unsigned*)p_wqo;
    g.C[1] = p_qo; g.sc[1] = SCALE_F * LOG2E_F; g.md[1] = 1;
    g.A[2] = (const unsigned*)p_kf; g.W[2] = (const unsigned*)p_wks;
    g.C[2] = p_ks; g.sc[2] = 1.0f;   g.md[2] = 1;
    g.A[3] = (const unsigned*)p_kf; g.W[3] = (const unsigned*)p_wko;
    g.C[3] = p_ko; g.sc[3] = 1.0f;   g.md[3] = 1;
    g.A[4] = (const unsigned*)p_vf; g.W[4] = (const unsigned*)p_wv;
    g.C[4] = p_vh; g.sc[4] = 1.0f;   g.md[4] = 2;

    dim3 ggrid(4, N_TOK / 128, 5);
    proj16_kernel<<<ggrid, 256>>>(g);

    dim3 agrid(L_ / 32, B_);
    attn_kernel<<<agrid, 512, AT_SMEM_BYTES>>>(mask, qid, kid, attn_out);

    dim3 fgrid(4, N_TOK / 128);
    fc16_kernel<<<fgrid, 256>>>((const unsigned*)p_ctx,
                                (const unsigned*)p_fcw, out, fcb);
}

// round 15
// speedup vs baseline: 1.7794x; 1.0188x over previous
#include <cuda_runtime.h>
#include <cuda_fp16.h>
#include <math_constants.h>

#define B_  8
#define L_  1024
#define S_  1024
#define D_  256
#define V_  256
#define H_  8

#define N_TOK (B_*L_)
#define SCALE_F 0.17677669529663687f
#define LOG2E_F 1.4426950408889634f

// pair permutation for m16n8k16 fragment adjacency: p in 0..7
__host__ __device__ __forceinline__ int permp(int p)
{
    return ((p & 3) << 1) | (p >> 2);
}

// ---------------- scratch (static device arrays: allocation-free) ----------
__device__ __half g_qf[N_TOK*D_];
__device__ __half g_kf[N_TOK*D_];
__device__ __half g_vf[N_TOK*D_];
__device__ __half g_wqs[D_*D_], g_wqo[D_*D_], g_wks[D_*D_];
__device__ __half g_wko[D_*D_], g_wv[D_*D_], g_fcwh[V_*V_];
__device__ __half g_mh[N_TOK*S_];     // mask * log2e, fp16

__device__ __half g_qs[N_TOK*D_];
__device__ __half g_qo[N_TOK*D_];
__device__ __half g_ks[N_TOK*D_];
__device__ __half g_ko[N_TOK*D_];
__device__ __half g_vh[N_TOK*D_];

// ---------------- exp2 on the MUFU pipe -------------------------------------
__device__ __forceinline__ float ex2f(float x)
{
    float r;
    asm("ex2.approx.ftz.f32 %0, %1;" : "=f"(r) : "f"(x));
    return r;
}

__device__ __forceinline__ void mma_f16(float c[4], const unsigned a[4],
                                        const unsigned b[2])
{
    asm("mma.sync.aligned.m16n8k16.row.col.f32.f16.f16.f32 "
        "{%0,%1,%2,%3}, {%4,%5,%6,%7}, {%8,%9}, {%0,%1,%2,%3};"
        : "+f"(c[0]), "+f"(c[1]), "+f"(c[2]), "+f"(c[3])
        : "r"(a[0]), "r"(a[1]), "r"(a[2]), "r"(a[3]),
          "r"(b[0]), "r"(b[1]));
}

// ---------------------------------------------------------------------------
// Prep: fp32 -> fp16 pair-permuted (K=256 rows).
// ---------------------------------------------------------------------------
struct Prep9 {
    const float* src[9];
    __half*      dst[9];
    int          n[9];
};

__global__ __launch_bounds__(256)
void prep_kernel(Prep9 P)
{
    int z = blockIdx.y;
    int idx = blockIdx.x * 256 + threadIdx.x;
    int i2 = idx * 2;
    if (i2 >= P.n[z]) return;
    float2 v = *reinterpret_cast<const float2*>(&P.src[z][i2]);
    int c = i2 & 255;
    int pos = (c & ~15) + permp((c & 15) >> 1) * 2;
    *reinterpret_cast<__half2*>(&P.dst[z][(size_t)(i2 >> 8) * 256 + pos]) =
        __floats2half2_rn(v.x, v.y);
}

__global__ __launch_bounds__(256)
void prep_mask_kernel(const float* __restrict__ m, __half* __restrict__ mh)
{
    size_t i = ((size_t)blockIdx.x * 256 + threadIdx.x) * 4;
    float4 v = *reinterpret_cast<const float4*>(&m[i]);
    __half2 a = __floats2half2_rn(v.x * LOG2E_F, v.y * LOG2E_F);
    __half2 b = __floats2half2_rn(v.z * LOG2E_F, v.w * LOG2E_F);
    uint2 o;
    o.x = *reinterpret_cast<unsigned*>(&a);
    o.y = *reinterpret_cast<unsigned*>(&b);
    *reinterpret_cast<uint2*>(&mh[i]) = o;
}

// ---------------------------------------------------------------------------
// gemm16: warp tile 32x32, block tile 128m x 64n, 256 thr, 3 blocks/SM.
// mode 1: fp16 permuted | mode 2: v blocked
// ---------------------------------------------------------------------------
__device__ __forceinline__ void gemm16_body(
    const unsigned* __restrict__ A, const unsigned* __restrict__ Bw,
    void* __restrict__ Cout, float scale, int mode)
{
    const int t    = threadIdx.x;
    const int w    = t >> 5;
    const int lane = t & 31;
    const int gid  = lane >> 2;
    const int tid4 = lane & 3;

    const int m0 = blockIdx.y * 128 + (w & 3) * 32;
    const int n0 = blockIdx.x * 64 + (w >> 2) * 32;

    float c[2][4][4];
#pragma unroll
    for (int rt = 0; rt < 2; rt++)
#pragma unroll
        for (int nt = 0; nt < 4; nt++)
#pragma unroll
            for (int e = 0; e < 4; e++) c[rt][nt][e] = 0.f;

#pragma unroll 4
    for (int kg = 0; kg < 16; kg++) {
        const int ko = kg * 8 + 2 * tid4;
        unsigned a[2][4];
#pragma unroll
        for (int rt = 0; rt < 2; rt++) {
            uint2 lo = *reinterpret_cast<const uint2*>(
                &A[(size_t)(m0 + rt * 16 + gid) * 128 + ko]);
            uint2 hi = *reinterpret_cast<const uint2*>(
                &A[(size_t)(m0 + rt * 16 + gid + 8) * 128 + ko]);
            a[rt][0] = lo.x; a[rt][1] = hi.x;
            a[rt][2] = lo.y; a[rt][3] = hi.y;
        }
#pragma unroll
        for (int nt = 0; nt < 4; nt++) {
            uint2 bb = *reinterpret_cast<const uint2*>(
                &Bw[(size_t)(n0 + nt * 8 + gid) * 128 + ko]);
            unsigned bfr[2] = {bb.x, bb.y};
            mma_f16(c[0][nt], a[0], bfr);
            mma_f16(c[1][nt], a[1], bfr);
        }
    }

    if (mode == 1) {
        __half* Ch = (__half*)Cout;
#pragma unroll
        for (int nt = 0; nt < 4; nt++) {
            int col = n0 + nt * 8 + 2 * tid4;
            int pos = (col & ~15) + permp((col & 15) >> 1) * 2;
#pragma unroll
            for (int rt = 0; rt < 2; rt++) {
                int r0 = m0 + rt * 16 + gid;
                *reinterpret_cast<__half2*>(&Ch[(size_t)r0 * 256 + pos]) =
                    __floats2half2_rn(c[rt][nt][0] * scale,
                                      c[rt][nt][1] * scale);
                *reinterpret_cast<__half2*>(&Ch[(size_t)(r0 + 8) * 256 + pos]) =
                    __floats2half2_rn(c[rt][nt][2] * scale,
                                      c[rt][nt][3] * scale);
            }
        }
    } else {
        __half* Ch = (__half*)Cout;
#pragma unroll
        for (int rt = 0; rt < 2; rt++)
#pragma unroll
            for (int rp = 0; rp < 2; rp++) {
                int r  = m0 + rt * 16 + gid + 8 * rp;
                int bb2 = r >> 10;
                int s  = r & 1023;
                int ph = permp((s & 15) >> 1) * 2 + (s & 1);
                size_t base0 = ((size_t)(bb2 * 64 + (s >> 4))) * 8;
#pragma unroll
                for (int nt = 0; nt < 4; nt++) {
#pragma unroll
                    for (int e = 0; e < 2; e++) {
                        int n = n0 + nt * 8 + 2 * tid4 + e;
                        size_t hi = ((base0 + (n >> 5)) * 32 + (n & 31)) * 16 + ph;
                        Ch[hi] = __float2half(c[rt][nt][2 * rp + e]);
                    }
                }
            }
    }
}

struct G5 {
    const unsigned* A[5];
    const unsigned* W[5];
    void*           C[5];
    float           sc[5];
    int             md[5];
};

__global__ __launch_bounds__(256, 3)
void proj16_kernel(G5 g)
{
    int z = blockIdx.z;
    gemm16_body(g.A[z], g.W[z], g.C[z], g.sc[z], g.md[z]);
}

// ---------------------------------------------------------------------------
// Attention + fused fc. Head-paired attn_out RMW, log2-domain EX2 softmax,
// ctx kept in registers, fc executed in-block at the end.
// smem: score [32][1036] fp32 (reused as sctx uints [32][132] for fc)
//       eh uint[32][516] | red [4][32][36] | inv[64] | qid 32 | kid 1024
// ---------------------------------------------------------------------------
#define SC_STR 1036
#define EH_STR 516
#define AT_SMEM_BYTES ((32*SC_STR + 32*EH_STR + 4608 + 64 + 32 + 1024) * 4)

__device__ __forceinline__ void score_phase(
    int h, float* score,
    const int* qid_s, const int* kid_s,
    size_t qbase, size_t kbase, size_t mrow0,
    int cb, int gid, int tid4)
{
    unsigned aS[2][2][4], aO[2][2][4];
#pragma unroll
    for (int rt = 0; rt < 2; rt++) {
        const size_t r0 = (qbase + rt * 16 + gid) * D_ + h * 32;
        const size_t r1 = r0 + 8 * D_;
#pragma unroll
        for (int g = 0; g < 2; g++) {
            int off = g * 16 + 4 * tid4;
            uint2 lo = *reinterpret_cast<const uint2*>(&g_qs[r0 + off]);
            uint2 hi = *reinterpret_cast<const uint2*>(&g_qs[r1 + off]);
            aS[rt][g][0] = lo.x; aS[rt][g][1] = hi.x;
            aS[rt][g][2] = lo.y; aS[rt][g][3] = hi.y;
            lo = *reinterpret_cast<const uint2*>(&g_qo[r0 + off]);
            hi = *reinterpret_cast<const uint2*>(&g_qo[r1 + off]);
            aO[rt][g][0] = lo.x; aO[rt][g][1] = hi.x;
            aO[rt][g][2] = lo.y; aO[rt][g][3] = hi.y;
        }
    }
    int qi[2][2];
#pragma unroll
    for (int rt = 0; rt < 2; rt++) {
        qi[rt][0] = qid_s[rt * 16 + gid];
        qi[rt][1] = qid_s[rt * 16 + gid + 8];
    }

#pragma unroll 2
    for (int nt = 0; nt < 8; nt++) {
        const int sK   = cb + nt * 8 + gid;
        const int scol = cb + nt * 8 + 2 * tid4;

        unsigned bS[2][2], bO[2][2];
        const size_t krow = (kbase + sK) * D_ + h * 32;
#pragma unroll
        for (int g = 0; g < 2; g++) {
            int off = g * 16 + 4 * tid4;
            uint2 v = *reinterpret_cast<const uint2*>(&g_ks[krow + off]);
            bS[g][0] = v.x; bS[g][1] = v.y;
            v = *reinterpret_cast<const uint2*>(&g_ko[krow + off]);
            bO[g][0] = v.x; bO[g][1] = v.y;
        }

        int2 ki = *reinterpret_cast<const int2*>(&kid_s[scol]);
        __half2 mf[2][2];
#pragma unroll
        for (int rt = 0; rt < 2; rt++)
#pragma unroll
            for (int rp = 0; rp < 2; rp++) {
                int row = rt * 16 + gid + 8 * rp;
                mf[rt][rp] = *reinterpret_cast<const __half2*>(
                    &g_mh[mrow0 + (size_t)row * S_ + scol]);
            }

        float cS[2][4] = {{0,0,0,0},{0,0,0,0}};
        float cO[2][4] = {{0,0,0,0},{0,0,0,0}};
#pragma unroll
        for (int g = 0; g < 2; g++)
#pragma unroll
            for (int rt = 0; rt < 2; rt++) {
                mma_f16(cS[rt], aS[rt][g], bS[g]);
                mma_f16(cO[rt], aO[rt][g], bO[g]);
            }

        // log2-domain scores; mask already scaled by log2e (fp16).
#pragma unroll
        for (int rt = 0; rt < 2; rt++)
#pragma unroll
            for (int rp = 0; rp < 2; rp++) {
                int row = rt * 16 + gid + 8 * rp;
                float s0 = (qi[rt][rp] == ki.x) ? cS[rt][2*rp]   : cO[rt][2*rp];
                float s1 = (qi[rt][rp] == ki.y) ? cS[rt][2*rp+1] : cO[rt][2*rp+1];
                float2 m2 = __half22float2(mf[rt][rp]);
                *reinterpret_cast<float2*>(&score[row * SC_STR + scol]) =
                    make_float2(s0 + m2.x, s1 + m2.y);
            }
    }
}

__device__ __forceinline__ void pv_phase(
    int h, const unsigned* __restrict__ ebase, int estride, bool skew,
    float* red, int b, int nc, int sh, int gid, int tid4)
{
    float cv[2][4] = {{0,0,0,0},{0,0,0,0}};
    const size_t vb0 = ((((size_t)(b * 64 + sh * 16) * 8 + h) * 32 +
                         nc * 8 + gid)) * 8 + 2 * tid4;
    const unsigned* vh_u = reinterpret_cast<const unsigned*>(g_vh);

#pragma unroll 4
    for (int kstep = 0; kstep < 16; kstep++) {
        uint2 bvv = *reinterpret_cast<const uint2*>(
            &vh_u[vb0 + (size_t)kstep * 2048]);
        unsigned bfrag[2] = {bvv.x, bvv.y};
        const int k8 = sh * 128 + kstep * 8;
#pragma unroll
        for (int rt = 0; rt < 2; rt++) {
            int row0 = rt * 16 + gid;
            int row1 = row0 + 8;
            const unsigned* e0 = ebase + row0 * estride +
                                 (skew ? (((row0 >> 2) & 1) << 2) : 0);
            const unsigned* e1 = ebase + row1 * estride +
                                 (skew ? (((row1 >> 2) & 1) << 2) : 0);
            unsigned av[4];
            av[0] = e0[k8 + tid4];
            av[1] = e1[k8 + tid4];
            av[2] = e0[k8 + tid4 + 4];
            av[3] = e1[k8 + tid4 + 4];
            mma_f16(cv[rt], av, bfrag);
        }
    }

#pragma unroll
    for (int rt = 0; rt < 2; rt++)
#pragma unroll
        for (int rp = 0; rp < 2; rp++) {
            int row = rt * 16 + gid + 8 * rp;
            *reinterpret_cast<float2*>(
                &red[sh * 1152 + row * 36 + nc * 8 + 2 * tid4]) =
                make_float2(cv[rt][2*rp], cv[rt][2*rp+1]);
        }
}

__global__ __launch_bounds__(512, 1)
void attn_kernel(const int* __restrict__ qid,
                 const int* __restrict__ kid,
                 float* __restrict__ attn_out,
                 float* __restrict__ out,
                 const float* __restrict__ fcb)
{
    extern __shared__ float sm[];
    float*    score = sm;                            // [32][1036] fp32
    unsigned* eh    = (unsigned*)(sm + 32 * SC_STR); // [32][516] half2
    float*    red   = sm + 32 * SC_STR + 32 * EH_STR;// [4][32][36]
    float*    inv   = red + 4608;                    // [64]
    int*      qid_s = (int*)(inv + 64);              // [32]
    int*      kid_s = qid_s + 32;                    // [1024]

    const int b    = blockIdx.y;
    const int l0   = blockIdx.x * 32;
    const int t    = threadIdx.x;
    const int lane = t & 31;
    const int w    = t >> 5;
    const int gid  = lane >> 2;
    const int tid4 = lane & 3;

    const size_t qbase = (size_t)(b * L_ + l0);
    const size_t kbase = (size_t)(b * S_);
    const size_t mrow0 = qbase * S_;

    const int cb = w * 64;
    const int nc = w & 3;
    const int sh = w >> 2;

    for (int i = t; i < S_; i += 512) kid_s[i] = kid[b * S_ + i];
    if (t < 32) qid_s[t] = qid[b * L_ + l0 + t];

    unsigned ctxr[8];   // per-thread ctx half2 for (row=t>>4, d0=(t&15)*2)

    for (int ph = 0; ph < 4; ph++) {
        const int h0 = 2 * ph, h1 = h0 + 1;
        __syncthreads();   // ids visible (ph=0); strip/eh/red free (ph>0)

        // ===== head h0: score =====
        score_phase(h0, score, qid_s, kid_s, qbase, kbase, mrow0,
                    cb, gid, tid4);
        __syncthreads();

        // ===== softmax h0 -> ehA (fp16), inv[row] =====
#pragma unroll
        for (int rr = 0; rr < 2; rr++) {
            int row = 2 * w + rr;
            float4* pr = (float4*)(score + row * SC_STR);
            unsigned* er = eh + row * EH_STR;
            float mx = -CUDART_INF_F;
#pragma unroll
            for (int u8 = 0; u8 < 8; u8++) {
                float4 x = pr[lane + 32 * u8];
                mx = fmaxf(mx, fmaxf(fmaxf(x.x, x.y), fmaxf(x.z, x.w)));
            }
#pragma unroll
            for (int o = 16; o > 0; o >>= 1)
                mx = fmaxf(mx, __shfl_xor_sync(0xffffffffu, mx, o));
            float s = 0.f;
#pragma unroll
            for (int u8 = 0; u8 < 8; u8++) {
                int idx = lane + 32 * u8;
                float4 x = pr[idx];
                x.x = ex2f(x.x - mx); x.y = ex2f(x.y - mx);
                x.z = ex2f(x.z - mx); x.w = ex2f(x.w - mx);
                s += (x.x + x.y) + (x.z + x.w);
                __half2 h01 = __floats2half2_rn(x.x, x.y);
                __half2 h23 = __floats2half2_rn(x.z, x.w);
                uint2 ev;
                ev.x = *reinterpret_cast<unsigned*>(&h01);
                ev.y = *reinterpret_cast<unsigned*>(&h23);
                *reinterpret_cast<uint2*>(&er[2 * idx]) = ev;
            }
#pragma unroll
            for (int o = 16; o > 0; o >>= 1)
                s += __shfl_xor_sync(0xffffffffu, s, o);
            if (lane == 0) inv[row] = 1.0f / s;
        }
        __syncthreads();

        // ===== PV h0 (reads ehA) =====
        pv_phase(h0, eh, EH_STR, false, red, b, nc, sh, gid, tid4);
        __syncthreads();

        // ===== ctx h0 (to regs) + score h1 =====
        {
            int row = t >> 4;
            int d0  = (t & 15) * 2;
            float s0 = red[row * 36 + d0]        + red[1152 + row * 36 + d0] +
                       red[2304 + row * 36 + d0] + red[3456 + row * 36 + d0];
            float s1 = red[row * 36 + d0 + 1]        + red[1152 + row * 36 + d0 + 1] +
                       red[2304 + row * 36 + d0 + 1] + red[3456 + row * 36 + d0 + 1];
            float iv = inv[row];
            __half2 hv = __floats2half2_rn(s0 * iv, s1 * iv);
            ctxr[h0] = *reinterpret_cast<unsigned*>(&hv);
        }
        score_phase(h1, score, qid_s, kid_s, qbase, kbase, mrow0,
                    cb, gid, tid4);
        __syncthreads();

        // ===== softmax h1: in-place fp16 downpack + combined RMW =====
#pragma unroll
        for (int rr = 0; rr < 2; rr++) {
            int row = 2 * w + rr;
            float4* pr = (float4*)(score + row * SC_STR);
            unsigned* eb = (unsigned*)score + row * SC_STR +
                           (((row >> 2) & 1) << 2);
            float4* out4 = reinterpret_cast<float4*>(
                attn_out + mrow0 + (size_t)row * S_);

            float mx = -CUDART_INF_F;
#pragma unroll
            for (int u8 = 0; u8 < 8; u8++) {
                float4 x = pr[lane + 32 * u8];
                mx = fmaxf(mx, fmaxf(fmaxf(x.x, x.y), fmaxf(x.z, x.w)));
            }
#pragma unroll
            for (int o = 16; o > 0; o >>= 1)
                mx = fmaxf(mx, __shfl_xor_sync(0xffffffffu, mx, o));

            float4 ov[8];
            if (ph > 0) {
#pragma unroll
                for (int u8 = 0; u8 < 8; u8++) ov[u8] = out4[lane + 32 * u8];
            }

            float s = 0.f;
#pragma unroll
            for (int u8 = 0; u8 < 8; u8++) {
                int idx = lane + 32 * u8;
                float4 x = pr[idx];
                x.x = ex2f(x.x - mx); x.y = ex2f(x.y - mx);
                x.z = ex2f(x.z - mx); x.w = ex2f(x.w - mx);
                s += (x.x + x.y) + (x.z + x.w);
                __half2 h01 = __floats2half2_rn(x.x, x.y);
                __half2 h23 = __floats2half2_rn(x.z, x.w);
                uint2 ev;
                ev.x = *reinterpret_cast<unsigned*>(&h01);
                ev.y = *reinterpret_cast<unsigned*>(&h23);
                *reinterpret_cast<uint2*>(&eb[2 * idx]) = ev;
            }
#pragma unroll
            for (int o = 16; o > 0; o >>= 1)
                s += __shfl_xor_sync(0xffffffffu, s, o);
            float iv1 = 1.0f / s;
            if (lane == 0) inv[32 + row] = iv1;

            float sv0 = inv[row] * 0.125f;
            float sv1 = iv1 * 0.125f;
            const uint2* eA2 = reinterpret_cast<const uint2*>(eh + row * EH_STR);
#pragma unroll
            for (int u8 = 0; u8 < 8; u8++) {
                int idx = lane + 32 * u8;
                uint2 a2 = eA2[idx];
                uint2 b2 = *reinterpret_cast<const uint2*>(&eb[2 * idx]);
                float2 a01 = __half22float2(*reinterpret_cast<__half2*>(&a2.x));
                float2 a23 = __half22float2(*reinterpret_cast<__half2*>(&a2.y));
                float2 b01 = __half22float2(*reinterpret_cast<__half2*>(&b2.x));
                float2 b23 = __half22float2(*reinterpret_cast<__half2*>(&b2.y));
                float4 o;
                if (ph == 0) {
                    o.x = a01.x * sv0 + b01.x * sv1;
                    o.y = a01.y * sv0 + b01.y * sv1;
                    o.z = a23.x * sv0 + b23.x * sv1;
                    o.w = a23.y * sv0 + b23.y * sv1;
                } else {
                    o.x = fmaf(a01.x, sv0, fmaf(b01.x, sv1, ov[u8].x));
                    o.y = fmaf(a01.y, sv0, fmaf(b01.y, sv1, ov[u8].y));
                    o.z = fmaf(a23.x, sv0, fmaf(b23.x, sv1, ov[u8].z));
                    o.w = fmaf(a23.y, sv0, fmaf(b23.y, sv1, ov[u8].w));
                }
                out4[idx] = o;
            }
        }
        __syncthreads();

        // ===== PV h1 (packed e in score strip, uint stride 1036) =====
        pv_phase(h1, (const unsigned*)score, SC_STR, true,
                 red, b, nc, sh, gid, tid4);
        __syncthreads();

        // ===== ctx h1 (to regs) =====
        {
            int row = t >> 4;
            int d0  = (t & 15) * 2;
            float s0 = red[row * 36 + d0]        + red[1152 + row * 36 + d0] +
                       red[2304 + row * 36 + d0] + red[3456 + row * 36 + d0];
            float s1 = red[row * 36 + d0 + 1]        + red[1152 + row * 36 + d0 + 1] +
                       red[2304 + row * 36 + d0 + 1] + red[3456 + row * 36 + d0 + 1];
            float iv = inv[32 + row];
            __half2 hv = __floats2half2_rn(s0 * iv, s1 * iv);
            ctxr[h1] = *reinterpret_cast<unsigned*>(&hv);
        }
    }

    // ================== fused fc ==================
    __syncthreads();   // score strip free (PV h1 of ph=3 done)
    unsigned* sctx = (unsigned*)score;   // [32][132] uints (permuted fp16 ctx)
    {
        int row = t >> 4;
        int d0  = (t & 15) * 2;
#pragma unroll
        for (int h = 0; h < 8; h++) {
            int n = h * 32 + d0;
            int pos = (n & ~15) + permp((n & 15) >> 1) * 2;
            sctx[row * 132 + (pos >> 1)] = ctxr[h];
        }
    }
    __syncthreads();

    // warp w -> output cols w*16 .. w*16+15, all 32 rows
    {
        const unsigned* fw = reinterpret_cast<const unsigned*>(g_fcwh);
        float c[2][2][4];
#pragma unroll
        for (int rt = 0; rt < 2; rt++)
#pragma unroll
            for (int nt = 0; nt < 2; nt++)
#pragma unroll
                for (int e = 0; e < 4; e++) c[rt][nt][e] = 0.f;

#pragma unroll 4
        for (int kg = 0; kg < 16; kg++) {
            const int ko = kg * 8 + 2 * tid4;
            unsigned a[2][4];
#pragma unroll
            for (int rt = 0; rt < 2; rt++) {
                uint2 lo = *reinterpret_cast<const uint2*>(
                    &sctx[(rt * 16 + gid) * 132 + ko]);
                uint2 hi = *reinterpret_cast<const uint2*>(
                    &sctx[(rt * 16 + gid + 8) * 132 + ko]);
                a[rt][0] = lo.x; a[rt][1] = hi.x;
                a[rt][2] = lo.y; a[rt][3] = hi.y;
            }
#pragma unroll
            for (int nt = 0; nt < 2; nt++) {
                uint2 bb = *reinterpret_cast<const uint2*>(
                    &fw[(size_t)(w * 16 + nt * 8 + gid) * 128 + ko]);
                unsigned bfr[2] = {bb.x, bb.y};
                mma_f16(c[0][nt], a[0], bfr);
                mma_f16(c[1][nt], a[1], bfr);
            }
        }

#pragma unroll
        for (int nt = 0; nt < 2; nt++) {
            int col = w * 16 + nt * 8 + 2 * tid4;
            float b0 = fcb[col], b1 = fcb[col + 1];
#pragma unroll
            for (int rt = 0; rt < 2; rt++) {
                int r0 = rt * 16 + gid;
                *reinterpret_cast<float2*>(
                    &out[(qbase + r0) * 256 + col]) =
                    make_float2(c[rt][nt][0] + b0, c[rt][nt][1] + b1);
                *reinterpret_cast<float2*>(
                    &out[(qbase + r0 + 8) * 256 + col]) =
                    make_float2(c[rt][nt][2] + b0, c[rt][nt][3] + b1);
            }
        }
    }
}

// ---------------------------------------------------------------------------
extern "C" void kernel_launch(void* const* d_in, const int* in_sizes, int n_in,
                              void* d_out, int out_size)
{
    const float* q    = (const float*)d_in[0];
    const float* k    = (const float*)d_in[1];
    const float* v    = (const float*)d_in[2];
    const int*   qid  = (const int*)d_in[3];
    const int*   kid  = (const int*)d_in[4];
    const float* mask = (const float*)d_in[5];
    const float* wqs  = (const float*)d_in[6];
    const float* wqo  = (const float*)d_in[7];
    const float* wks  = (const float*)d_in[8];
    const float* wko  = (const float*)d_in[9];
    const float* wv   = (const float*)d_in[10];
    const float* fcw  = (const float*)d_in[11];
    const float* fcb  = (const float*)d_in[12];

    float* out      = (float*)d_out;
    float* attn_out = out + (size_t)B_ * L_ * V_;

    void *p_qf, *p_kf, *p_vf, *p_wqs, *p_wqo, *p_wks, *p_wko, *p_wv, *p_fcw;
    void *p_qs, *p_qo, *p_ks, *p_ko, *p_vh, *p_mh;
    cudaGetSymbolAddress(&p_qf,  g_qf);
    cudaGetSymbolAddress(&p_kf,  g_kf);
    cudaGetSymbolAddress(&p_vf,  g_vf);
    cudaGetSymbolAddress(&p_wqs, g_wqs);
    cudaGetSymbolAddress(&p_wqo, g_wqo);
    cudaGetSymbolAddress(&p_wks, g_wks);
    cudaGetSymbolAddress(&p_wko, g_wko);
    cudaGetSymbolAddress(&p_wv,  g_wv);
    cudaGetSymbolAddress(&p_fcw, g_fcwh);
    cudaGetSymbolAddress(&p_qs,  g_qs);
    cudaGetSymbolAddress(&p_qo,  g_qo);
    cudaGetSymbolAddress(&p_ks,  g_ks);
    cudaGetSymbolAddress(&p_ko,  g_ko);
    cudaGetSymbolAddress(&p_vh,  g_vh);
    cudaGetSymbolAddress(&p_mh,  g_mh);

    cudaFuncSetAttribute(attn_kernel,
                         cudaFuncAttributeMaxDynamicSharedMemorySize,
                         AT_SMEM_BYTES);

    Prep9 P;
    P.src[0] = q;   P.dst[0] = (__half*)p_qf;  P.n[0] = N_TOK * D_;
    P.src[1] = k;   P.dst[1] = (__half*)p_kf;  P.n[1] = N_TOK * D_;
    P.src[2] = v;   P.dst[2] = (__half*)p_vf;  P.n[2] = N_TOK * D_;
    P.src[3] = wqs; P.dst[3] = (__half*)p_wqs; P.n[3] = D_ * D_;
    P.src[4] = wqo; P.dst[4] = (__half*)p_wqo; P.n[4] = D_ * D_;
    P.src[5] = wks; P.dst[5] = (__half*)p_wks; P.n[5] = D_ * D_;
    P.src[6] = wko; P.dst[6] = (__half*)p_wko; P.n[6] = D_ * D_;
    P.src[7] = wv;  P.dst[7] = (__half*)p_wv;  P.n[7] = D_ * D_;
    P.src[8] = fcw; P.dst[8] = (__half*)p_fcw; P.n[8] = V_ * V_;
    dim3 pgrid(N_TOK * D_ / 512, 9);
    prep_kernel<<<pgrid, 256>>>(P);

    // mask * log2e -> fp16
    prep_mask_kernel<<<(N_TOK * S_) / 1024, 256>>>(mask, (__half*)p_mh);

    // q projections pre-scaled by SCALE*log2e -> scores in log2 domain
    G5 g;
    g.A[0] = (const unsigned*)p_qf; g.W[0] = (const unsigned*)p_wqs;
    g.C[0] = p_qs; g.sc[0] = SCALE_F * LOG2E_F; g.md[0] = 1;
    g.A[1] = (const unsigned*)p_qf; g.W[1] = (const unsigned*)p_wqo;
    g.C[1] = p_qo; g.sc[1] = SCALE_F * LOG2E_F; g.md[1] = 1;
    g.A[2] = (const unsigned*)p_kf; g.W[2] = (const unsigned*)p_wks;
    g.C[2] = p_ks; g.sc[2] = 1.0f;   g.md[2] = 1;
    g.A[3] = (const unsigned*)p_kf; g.W[3] = (const unsigned*)p_wko;
    g.C[3] = p_ko; g.sc[3] = 1.0f;   g.md[3] = 1;
    g.A[4] = (const unsigned*)p_vf; g.W[4] = (const unsigned*)p_wv;
    g.C[4] = p_vh; g.sc[4] = 1.0f;   g.md[4] = 2;

    dim3 ggrid(4, N_TOK / 128, 5);
    proj16_kernel<<<ggrid, 256>>>(g);

    dim3 agrid(L_ / 32, B_);
    attn_kernel<<<agrid, 512, AT_SMEM_BYTES>>>(qid, kid, attn_out, out, fcb);
}